// round 6
// baseline (speedup 1.0000x reference)
#include <cuda_runtime.h>
#include <cuda_fp16.h>
#include <cstdint>

// ---------------------------------------------------------------------------
// GIN regression: 3x (scatter-add agg + MLP(64->64->64) + BN-affine + ReLU),
// then per-graph mean pool + 2-layer head -> [128].
//
// Node features h stored in FP16 (halves L2 gather traffic, which is the
// measured bottleneck). All accumulation/GEMM math in fp32.
//   phase 1: warp-per-node CSR gather (half2 loads -> fp32 acc) into shared
//            transposed swizzled tile sh_t[k][node]
//   phase 2: register-blocked 64x64x64 fp32 GEMM x2, bias/ReLU/BN in regs,
//            half output stores.
// ---------------------------------------------------------------------------

#define NMAX 100000
#define EMAX 1600000
#define GMAX 128
#define TILE 64          // nodes per block tile

// scratch (device globals: allocation-free)
__device__ __half g_hA[(size_t)NMAX * 64];
__device__ __half g_hB[(size_t)NMAX * 64];
__device__ int    g_deg[NMAX];
__device__ int    g_rowptr[NMAX + 1];
__device__ int    g_cursor[NMAX];
__device__ int    g_col[EMAX];
__device__ float  g_pooled[GMAX * 64];

// ---------------------------------------------------------------------------
__global__ void zero_deg_kernel(int n) {
    int i = blockIdx.x * blockDim.x + threadIdx.x;
    if (i < n) g_deg[i] = 0;
}

__global__ void cvt_kernel(const float* __restrict__ x, int n64) {
    int i = (blockIdx.x * blockDim.x + threadIdx.x) * 4;
    if (i < n64) {
        float4 f = *(const float4*)(x + i);
        *(__half2*)(g_hA + i)     = __floats2half2_rn(f.x, f.y);
        *(__half2*)(g_hA + i + 2) = __floats2half2_rn(f.z, f.w);
    }
}

__global__ void hist_kernel(const int* __restrict__ ei, int E) {
    for (int e = blockIdx.x * blockDim.x + threadIdx.x; e < E; e += gridDim.x * blockDim.x) {
        int d = ei[E + e];   // dst row of edge_index[2, E]
        atomicAdd(&g_deg[d], 1);
    }
}

// single-block exclusive scan over deg -> rowptr (+ cursor copy).
// 1024 threads x 4 elements per chunk -> 25 chunks for n ~ 100001.
__global__ void scan_kernel(int n) {
    __shared__ int wsum[32];
    __shared__ int carry_s;
    const int tid = threadIdx.x;
    const int lane = tid & 31, wid = tid >> 5;
    if (tid == 0) carry_s = 0;
    __syncthreads();
    for (int base = 0; base < n; base += 4096) {
        const int i0 = base + tid * 4;
        int v0 = (i0 + 0 < n) ? g_deg[i0 + 0] : 0;
        int v1 = (i0 + 1 < n) ? g_deg[i0 + 1] : 0;
        int v2 = (i0 + 2 < n) ? g_deg[i0 + 2] : 0;
        int v3 = (i0 + 3 < n) ? g_deg[i0 + 3] : 0;
        const int tsum = ((v0 + v1) + (v2 + v3));
        int x = tsum;
        #pragma unroll
        for (int o = 1; o < 32; o <<= 1) {
            int y = __shfl_up_sync(0xffffffffu, x, o);
            if (lane >= o) x += y;
        }
        if (lane == 31) wsum[wid] = x;
        __syncthreads();
        if (wid == 0) {
            int w = wsum[lane];
            #pragma unroll
            for (int o = 1; o < 32; o <<= 1) {
                int y = __shfl_up_sync(0xffffffffu, w, o);
                if (lane >= o) w += y;
            }
            wsum[lane] = w;
        }
        __syncthreads();
        int p = x - tsum + (wid > 0 ? wsum[wid - 1] : 0) + carry_s;
        if (i0 + 0 < n) { g_rowptr[i0 + 0] = p; g_cursor[i0 + 0] = p; } p += v0;
        if (i0 + 1 < n) { g_rowptr[i0 + 1] = p; g_cursor[i0 + 1] = p; } p += v1;
        if (i0 + 2 < n) { g_rowptr[i0 + 2] = p; g_cursor[i0 + 2] = p; } p += v2;
        if (i0 + 3 < n) { g_rowptr[i0 + 3] = p; g_cursor[i0 + 3] = p; } p += v3;
        __syncthreads();                 // readers of carry_s/wsum done
        if (tid == 1023) carry_s = p;    // inclusive through chunk end
        __syncthreads();
    }
    if (tid == 0) g_rowptr[n] = carry_s; // == E
}

__global__ void fill_kernel(const int* __restrict__ ei, int E) {
    for (int e = blockIdx.x * blockDim.x + threadIdx.x; e < E; e += gridDim.x * blockDim.x) {
        int s = ei[e];
        int d = ei[E + e];
        int p = atomicAdd(&g_cursor[d], 1);
        g_col[p] = s;
    }
}

// ---------------------------------------------------------------------------
// swizzled transposed tile address: logical (channel/k row, node col m)
__device__ __forceinline__ int swz(int k, int m) {
    return k * 64 + ((m & 60) ^ ((k & 15) << 2)) + (m & 3);
}

__global__ __launch_bounds__(256, 4) void layer_kernel(
    int in_sel, int out_sel,
    const float* __restrict__ W1, const float* __restrict__ b1,
    const float* __restrict__ W2, const float* __restrict__ b2,
    const float* __restrict__ gamma, const float* __restrict__ beta,
    int n_nodes)
{
    const __half* __restrict__ hin  = (in_sel == 1) ? g_hA : g_hB;
    __half* __restrict__       hout = (out_sel == 1) ? g_hA : g_hB;

    __shared__ __align__(16) float W1s[64 * 64];   // 16 KB
    __shared__ __align__(16) float W2s[64 * 64];   // 16 KB
    __shared__ __align__(16) float sh_t[64 * 64];  // 16 KB (total = 48 KB static)

    for (int i = threadIdx.x; i < 64 * 64; i += 256) { W1s[i] = W1[i]; W2s[i] = W2[i]; }

    const int tid  = threadIdx.x;
    const int warp = tid >> 5, lane = tid & 31;
    const int ng4  = (tid & 15) * 4;   // node group (4 nodes)
    const int cg4  = (tid >> 4) * 4;   // channel group (4 channels)
    const int c0 = 2 * lane, c1 = 2 * lane + 1;

    // per-thread channel constants (registers, not shared)
    float b1r[4], b2r[4], gr[4], br[4];
    #pragma unroll
    for (int i = 0; i < 4; i++) {
        b1r[i] = b1[cg4 + i]; b2r[i] = b2[cg4 + i];
        gr[i]  = gamma[cg4 + i]; br[i] = beta[cg4 + i];
    }
    __syncthreads();

    const int ntiles = (n_nodes + TILE - 1) / TILE;
    for (int tile = blockIdx.x; tile < ntiles; tile += gridDim.x) {
        const int base = tile * TILE;

        // ---- phase 1: gather 64 nodes (warp-per-node, 8 nodes/warp) ----
        #pragma unroll 1
        for (int i = 0; i < 8; i++) {
            const int m = warp * 8 + i;
            const int node = base + m;
            if (node < n_nodes) {
                float2 acc = __half22float2(*(const __half2*)(hin + (size_t)node * 64 + c0)); // self
                int j = g_rowptr[node];
                const int jend = g_rowptr[node + 1];
                #pragma unroll 1
                for (; j + 8 <= jend; j += 8) {
                    int s[8];
                    #pragma unroll
                    for (int q = 0; q < 8; q++) s[q] = g_col[j + q];
                    __half2 v[8];
                    #pragma unroll
                    for (int q = 0; q < 8; q++)
                        v[q] = *(const __half2*)(hin + (size_t)s[q] * 64 + c0);
                    float2 f0 = __half22float2(v[0]), f1 = __half22float2(v[1]);
                    float2 f2 = __half22float2(v[2]), f3 = __half22float2(v[3]);
                    float2 f4 = __half22float2(v[4]), f5 = __half22float2(v[5]);
                    float2 f6 = __half22float2(v[6]), f7 = __half22float2(v[7]);
                    acc.x += ((f0.x + f1.x) + (f2.x + f3.x)) + ((f4.x + f5.x) + (f6.x + f7.x));
                    acc.y += ((f0.y + f1.y) + (f2.y + f3.y)) + ((f4.y + f5.y) + (f6.y + f7.y));
                }
                for (; j < jend; j++) {
                    float2 v = __half22float2(*(const __half2*)(hin + (size_t)g_col[j] * 64 + c0));
                    acc.x += v.x; acc.y += v.y;
                }
                sh_t[swz(c0, m)] = acc.x;      // transposed + swizzled store
                sh_t[swz(c1, m)] = acc.y;
            }
        }
        __syncthreads();

        // ---- phase 2a: U = relu(T^T W1 + b1), register-blocked ----
        float a00=0,a01=0,a02=0,a03=0, a10=0,a11=0,a12=0,a13=0;
        float a20=0,a21=0,a22=0,a23=0, a30=0,a31=0,a32=0,a33=0;
        #pragma unroll 8
        for (int k = 0; k < 64; k++) {
            const float4 a = *(const float4*)(sh_t + k * 64 + (ng4 ^ ((k & 15) << 2)));
            const float4 w = *(const float4*)(W1s + k * 64 + cg4);
            a00 = fmaf(w.x, a.x, a00); a01 = fmaf(w.x, a.y, a01); a02 = fmaf(w.x, a.z, a02); a03 = fmaf(w.x, a.w, a03);
            a10 = fmaf(w.y, a.x, a10); a11 = fmaf(w.y, a.y, a11); a12 = fmaf(w.y, a.z, a12); a13 = fmaf(w.y, a.w, a13);
            a20 = fmaf(w.z, a.x, a20); a21 = fmaf(w.z, a.y, a21); a22 = fmaf(w.z, a.z, a22); a23 = fmaf(w.z, a.w, a23);
            a30 = fmaf(w.w, a.x, a30); a31 = fmaf(w.w, a.y, a31); a32 = fmaf(w.w, a.z, a32); a33 = fmaf(w.w, a.w, a33);
        }
        a00 = fmaxf(a00 + b1r[0], 0.f); a01 = fmaxf(a01 + b1r[0], 0.f); a02 = fmaxf(a02 + b1r[0], 0.f); a03 = fmaxf(a03 + b1r[0], 0.f);
        a10 = fmaxf(a10 + b1r[1], 0.f); a11 = fmaxf(a11 + b1r[1], 0.f); a12 = fmaxf(a12 + b1r[1], 0.f); a13 = fmaxf(a13 + b1r[1], 0.f);
        a20 = fmaxf(a20 + b1r[2], 0.f); a21 = fmaxf(a21 + b1r[2], 0.f); a22 = fmaxf(a22 + b1r[2], 0.f); a23 = fmaxf(a23 + b1r[2], 0.f);
        a30 = fmaxf(a30 + b1r[3], 0.f); a31 = fmaxf(a31 + b1r[3], 0.f); a32 = fmaxf(a32 + b1r[3], 0.f); a33 = fmaxf(a33 + b1r[3], 0.f);

        __syncthreads();   // all GEMM1 reads of sh_t done
        // write U back into sh_t (already [chan][node] in registers)
        {
            int k0 = cg4;
            *(float4*)(sh_t + (k0 + 0) * 64 + (ng4 ^ (((k0 + 0) & 15) << 2))) = make_float4(a00, a01, a02, a03);
            *(float4*)(sh_t + (k0 + 1) * 64 + (ng4 ^ (((k0 + 1) & 15) << 2))) = make_float4(a10, a11, a12, a13);
            *(float4*)(sh_t + (k0 + 2) * 64 + (ng4 ^ (((k0 + 2) & 15) << 2))) = make_float4(a20, a21, a22, a23);
            *(float4*)(sh_t + (k0 + 3) * 64 + (ng4 ^ (((k0 + 3) & 15) << 2))) = make_float4(a30, a31, a32, a33);
        }
        __syncthreads();

        // ---- phase 2b: V = relu(gamma*(U^T W2 + b2) + beta) ----
        float v00=0,v01=0,v02=0,v03=0, v10=0,v11=0,v12=0,v13=0;
        float v20=0,v21=0,v22=0,v23=0, v30=0,v31=0,v32=0,v33=0;
        #pragma unroll 8
        for (int k = 0; k < 64; k++) {
            const float4 a = *(const float4*)(sh_t + k * 64 + (ng4 ^ ((k & 15) << 2)));
            const float4 w = *(const float4*)(W2s + k * 64 + cg4);
            v00 = fmaf(w.x, a.x, v00); v01 = fmaf(w.x, a.y, v01); v02 = fmaf(w.x, a.z, v02); v03 = fmaf(w.x, a.w, v03);
            v10 = fmaf(w.y, a.x, v10); v11 = fmaf(w.y, a.y, v11); v12 = fmaf(w.y, a.z, v12); v13 = fmaf(w.y, a.w, v13);
            v20 = fmaf(w.z, a.x, v20); v21 = fmaf(w.z, a.y, v21); v22 = fmaf(w.z, a.z, v22); v23 = fmaf(w.z, a.w, v23);
            v30 = fmaf(w.w, a.x, v30); v31 = fmaf(w.w, a.y, v31); v32 = fmaf(w.w, a.z, v32); v33 = fmaf(w.w, a.w, v33);
        }
        #define BNR(v, i) fmaxf(fmaf((v) + b2r[i], gr[i], br[i]), 0.f)
        v00 = BNR(v00, 0); v01 = BNR(v01, 0); v02 = BNR(v02, 0); v03 = BNR(v03, 0);
        v10 = BNR(v10, 1); v11 = BNR(v11, 1); v12 = BNR(v12, 1); v13 = BNR(v13, 1);
        v20 = BNR(v20, 2); v21 = BNR(v21, 2); v22 = BNR(v22, 2); v23 = BNR(v23, 2);
        v30 = BNR(v30, 3); v31 = BNR(v31, 3); v32 = BNR(v32, 3); v33 = BNR(v33, 3);
        #undef BNR

        // ---- store: register transpose -> hout[node][cg4..cg4+3] as half ----
        {
            int n0 = base + ng4;
            if (n0 + 0 < n_nodes) {
                __half2* d = (__half2*)(hout + (size_t)(n0 + 0) * 64 + cg4);
                d[0] = __floats2half2_rn(v00, v10); d[1] = __floats2half2_rn(v20, v30);
            }
            if (n0 + 1 < n_nodes) {
                __half2* d = (__half2*)(hout + (size_t)(n0 + 1) * 64 + cg4);
                d[0] = __floats2half2_rn(v01, v11); d[1] = __floats2half2_rn(v21, v31);
            }
            if (n0 + 2 < n_nodes) {
                __half2* d = (__half2*)(hout + (size_t)(n0 + 2) * 64 + cg4);
                d[0] = __floats2half2_rn(v02, v12); d[1] = __floats2half2_rn(v22, v32);
            }
            if (n0 + 3 < n_nodes) {
                __half2* d = (__half2*)(hout + (size_t)(n0 + 3) * 64 + cg4);
                d[0] = __floats2half2_rn(v03, v13); d[1] = __floats2half2_rn(v23, v33);
            }
        }
        __syncthreads();   // GEMM2 reads done before next tile's phase 1
    }
}

// ---------------------------------------------------------------------------
__device__ __forceinline__ int lower_bound_i(const int* a, int n, int key) {
    int lo = 0, hi = n;
    while (lo < hi) {
        int mid = (lo + hi) >> 1;
        if (a[mid] < key) lo = mid + 1; else hi = mid;
    }
    return lo;
}

__global__ void pool_kernel(const int* __restrict__ batch, int n_nodes) {
    const __half* __restrict__ h = g_hB;  // final layer output lives in g_hB
    const int g = blockIdx.x;             // 128 blocks, 256 threads
    const int lo = lower_bound_i(batch, n_nodes, g);
    const int hi = lower_bound_i(batch, n_nodes, g + 1);
    const int c = threadIdx.x & 63;
    const int r = threadIdx.x >> 6;       // 4 node-lanes
    float acc = 0.f;
    for (int i = lo + r; i < hi; i += 4) acc += __half2float(h[(size_t)i * 64 + c]);
    __shared__ float sh[256];
    sh[threadIdx.x] = acc;
    __syncthreads();
    if (threadIdx.x < 128) sh[threadIdx.x] += sh[threadIdx.x + 128];
    __syncthreads();
    if (threadIdx.x < 64) {
        float s = sh[threadIdx.x] + sh[threadIdx.x + 64];
        float cnt = (float)(hi - lo);
        g_pooled[g * 64 + threadIdx.x] = s / fmaxf(cnt, 1.f);
    }
}

__global__ void head_kernel(const float* __restrict__ fc1W, const float* __restrict__ fc1b,
                            const float* __restrict__ fc2W, const float* __restrict__ fc2b,
                            float* __restrict__ out, int G) {
    int g = blockIdx.x * blockDim.x + threadIdx.x;
    if (g >= G) return;
    float p[64];
    #pragma unroll
    for (int k = 0; k < 64; k++) p[k] = g_pooled[g * 64 + k];
    float o = fc2b[0];
    for (int j = 0; j < 32; j++) {
        float a = fc1b[j];
        #pragma unroll
        for (int k = 0; k < 64; k++) a = fmaf(p[k], fc1W[k * 32 + j], a);
        o = fmaf(fmaxf(a, 0.f), fc2W[j], o);
    }
    out[g] = o;
}

// ---------------------------------------------------------------------------
extern "C" void kernel_launch(void* const* d_in, const int* in_sizes, int n_in,
                              void* d_out, int out_size) {
    const float* x     = (const float*)d_in[0];
    const int*   ei    = (const int*)d_in[1];     // int32 edge_index [2, E]
    const int*   batch = (const int*)d_in[2];     // int32, sorted
    const float* W1    = (const float*)d_in[3];
    const float* b1    = (const float*)d_in[4];
    const float* W2    = (const float*)d_in[5];
    const float* b2    = (const float*)d_in[6];
    const float* gamma = (const float*)d_in[7];
    const float* beta  = (const float*)d_in[8];
    const float* fc1W  = (const float*)d_in[9];
    const float* fc1b  = (const float*)d_in[10];
    const float* fc2W  = (const float*)d_in[11];
    const float* fc2b  = (const float*)d_in[12];
    float*       out   = (float*)d_out;

    const int N = in_sizes[0] / 64;
    const int E = in_sizes[1] / 2;
    const int G = out_size;

    // --- CSR build (dst -> src) + x -> half conversion ---
    zero_deg_kernel<<<(N + 255) / 256, 256>>>(N);
    cvt_kernel<<<(N * 64 / 4 + 255) / 256, 256>>>(x, N * 64);
    hist_kernel<<<2048, 256>>>(ei, E);
    scan_kernel<<<1, 1024>>>(N);
    fill_kernel<<<2048, 256>>>(ei, E);

    // --- 3 fused GIN layers, ping-pong: A -> B -> A -> B ---
    const int LBLOCKS = 592;   // 4 blocks/SM resident, grid-stride over tiles
    layer_kernel<<<LBLOCKS, 256>>>(1, 2,
                                   W1 + 0 * 4096, b1 + 0 * 64, W2 + 0 * 4096, b2 + 0 * 64,
                                   gamma + 0 * 64, beta + 0 * 64, N);
    layer_kernel<<<LBLOCKS, 256>>>(2, 1,
                                   W1 + 1 * 4096, b1 + 1 * 64, W2 + 1 * 4096, b2 + 1 * 64,
                                   gamma + 1 * 64, beta + 1 * 64, N);
    layer_kernel<<<LBLOCKS, 256>>>(1, 2,
                                   W1 + 2 * 4096, b1 + 2 * 64, W2 + 2 * 4096, b2 + 2 * 64,
                                   gamma + 2 * 64, beta + 2 * 64, N);

    // --- mean pool + head ---
    pool_kernel<<<G, 256>>>(batch, N);
    head_kernel<<<1, 128>>>(fc1W, fc1b, fc2W, fc2b, out, G);
}

// round 7
// speedup vs baseline: 1.1695x; 1.1695x over previous
#include <cuda_runtime.h>
#include <cuda_fp16.h>
#include <cstdint>

// ---------------------------------------------------------------------------
// GIN regression: 3x (scatter-add agg + MLP(64->64->64) + BN-affine + ReLU),
// then per-graph mean pool + 2-layer head -> [128].
//
// Node features h stored in FP16 (halves L2 gather traffic). fp32 math.
// CSR build: hist (int atomics) + two-pass multi-block scan + fill.
// Layer: phase-1 warp-per-node gather into shared swizzled tile, phase-2
// register-blocked 64x64x64 fp32 GEMM x2.
// ---------------------------------------------------------------------------

#define NMAX 100000
#define EMAX 1600000
#define GMAX 128
#define TILE 64          // nodes per block tile
#define SCB  1024        // scan chunk (threads per scan block)

// scratch (device globals: allocation-free)
__device__ __half g_hA[(size_t)NMAX * 64];
__device__ __half g_hB[(size_t)NMAX * 64];
__device__ int    g_deg[NMAX];
__device__ int    g_rowptr[NMAX + 1];
__device__ int    g_cursor[NMAX];
__device__ int    g_col[EMAX];
__device__ int    g_bsum[128];
__device__ int    g_boff[128];
__device__ float  g_pooled[GMAX * 64];

// ---------------------------------------------------------------------------
__global__ void zero_deg_kernel(int n) {
    int i = blockIdx.x * blockDim.x + threadIdx.x;
    if (i < n) g_deg[i] = 0;
}

__global__ void cvt_kernel(const float* __restrict__ x, int n64) {
    int i = (blockIdx.x * blockDim.x + threadIdx.x) * 4;
    if (i < n64) {
        float4 f = *(const float4*)(x + i);
        *(__half2*)(g_hA + i)     = __floats2half2_rn(f.x, f.y);
        *(__half2*)(g_hA + i + 2) = __floats2half2_rn(f.z, f.w);
    }
}

__global__ void hist_kernel(const int* __restrict__ ei, int E) {
    const int2* dst2 = (const int2*)(ei + E);     // dst row, E even -> 8B aligned
    const int E2 = E >> 1;
    for (int e = blockIdx.x * blockDim.x + threadIdx.x; e < E2; e += gridDim.x * blockDim.x) {
        int2 d = dst2[e];
        atomicAdd(&g_deg[d.x], 1);
        atomicAdd(&g_deg[d.y], 1);
    }
}

// ---- two-pass scan: bsum (per-chunk totals) -> bscan (scan totals) -> scatter
__global__ void bsum_kernel(int n) {
    __shared__ int sh[32];
    int i = blockIdx.x * SCB + threadIdx.x;
    int v = (i < n) ? g_deg[i] : 0;
    #pragma unroll
    for (int o = 16; o > 0; o >>= 1) v += __shfl_down_sync(0xffffffffu, v, o);
    if ((threadIdx.x & 31) == 0) sh[threadIdx.x >> 5] = v;
    __syncthreads();
    if (threadIdx.x < 32) {
        int w = sh[threadIdx.x];
        #pragma unroll
        for (int o = 16; o > 0; o >>= 1) w += __shfl_down_sync(0xffffffffu, w, o);
        if (threadIdx.x == 0) g_bsum[blockIdx.x] = w;
    }
}

__global__ void bscan_kernel(int nb, int n) {   // 1 block, 1024 threads, nb<=1024
    __shared__ int wsum[32];
    const int tid = threadIdx.x, lane = tid & 31, wid = tid >> 5;
    int v = (tid < nb) ? g_bsum[tid] : 0;
    int x = v;
    #pragma unroll
    for (int o = 1; o < 32; o <<= 1) {
        int y = __shfl_up_sync(0xffffffffu, x, o);
        if (lane >= o) x += y;
    }
    if (lane == 31) wsum[wid] = x;
    __syncthreads();
    if (wid == 0) {
        int w = wsum[lane];
        #pragma unroll
        for (int o = 1; o < 32; o <<= 1) {
            int y = __shfl_up_sync(0xffffffffu, w, o);
            if (lane >= o) w += y;
        }
        wsum[lane] = w;
    }
    __syncthreads();
    int excl = x - v + (wid > 0 ? wsum[wid - 1] : 0);
    if (tid < nb) g_boff[tid] = excl;
    if (tid == nb - 1) g_rowptr[n] = excl + v;   // total == E
}

__global__ void scatter_scan_kernel(int n) {
    __shared__ int wsum[32];
    const int tid = threadIdx.x, lane = tid & 31, wid = tid >> 5;
    int i = blockIdx.x * SCB + tid;
    int v = (i < n) ? g_deg[i] : 0;
    int x = v;
    #pragma unroll
    for (int o = 1; o < 32; o <<= 1) {
        int y = __shfl_up_sync(0xffffffffu, x, o);
        if (lane >= o) x += y;
    }
    if (lane == 31) wsum[wid] = x;
    __syncthreads();
    if (wid == 0) {
        int w = wsum[lane];
        #pragma unroll
        for (int o = 1; o < 32; o <<= 1) {
            int y = __shfl_up_sync(0xffffffffu, w, o);
            if (lane >= o) w += y;
        }
        wsum[lane] = w;
    }
    __syncthreads();
    int excl = x - v + (wid > 0 ? wsum[wid - 1] : 0) + g_boff[blockIdx.x];
    if (i < n) { g_rowptr[i] = excl; g_cursor[i] = excl; }
}

__global__ void fill_kernel(const int* __restrict__ ei, int E) {
    const int2* src2 = (const int2*)ei;
    const int2* dst2 = (const int2*)(ei + E);
    const int E2 = E >> 1;
    for (int e = blockIdx.x * blockDim.x + threadIdx.x; e < E2; e += gridDim.x * blockDim.x) {
        int2 s = src2[e];
        int2 d = dst2[e];
        int p0 = atomicAdd(&g_cursor[d.x], 1);
        g_col[p0] = s.x;
        int p1 = atomicAdd(&g_cursor[d.y], 1);
        g_col[p1] = s.y;
    }
}

// ---------------------------------------------------------------------------
// swizzled transposed tile address: logical (channel/k row, node col m)
__device__ __forceinline__ int swz(int k, int m) {
    return k * 64 + ((m & 60) ^ ((k & 15) << 2)) + (m & 3);
}

__global__ __launch_bounds__(256, 4) void layer_kernel(
    int in_sel, int out_sel,
    const float* __restrict__ W1, const float* __restrict__ b1,
    const float* __restrict__ W2, const float* __restrict__ b2,
    const float* __restrict__ gamma, const float* __restrict__ beta,
    int n_nodes)
{
    const __half* __restrict__ hin  = (in_sel == 1) ? g_hA : g_hB;
    __half* __restrict__       hout = (out_sel == 1) ? g_hA : g_hB;

    __shared__ __align__(16) float W1s[64 * 64];   // 16 KB
    __shared__ __align__(16) float W2s[64 * 64];   // 16 KB
    __shared__ __align__(16) float sh_t[64 * 64];  // 16 KB (total = 48 KB static)

    for (int i = threadIdx.x; i < 64 * 64; i += 256) { W1s[i] = W1[i]; W2s[i] = W2[i]; }

    const int tid  = threadIdx.x;
    const int warp = tid >> 5, lane = tid & 31;
    const int ng4  = (tid & 15) * 4;   // node group (4 nodes)
    const int cg4  = (tid >> 4) * 4;   // channel group (4 channels)
    const int c0 = 2 * lane, c1 = 2 * lane + 1;

    float b1r[4], b2r[4], gr[4], br[4];
    #pragma unroll
    for (int i = 0; i < 4; i++) {
        b1r[i] = b1[cg4 + i]; b2r[i] = b2[cg4 + i];
        gr[i]  = gamma[cg4 + i]; br[i] = beta[cg4 + i];
    }
    __syncthreads();

    const int ntiles = (n_nodes + TILE - 1) / TILE;
    for (int tile = blockIdx.x; tile < ntiles; tile += gridDim.x) {
        const int base = tile * TILE;

        // ---- phase 1: gather 64 nodes (warp-per-node, 8 nodes/warp) ----
        #pragma unroll 1
        for (int i = 0; i < 8; i++) {
            const int m = warp * 8 + i;
            const int node = base + m;
            if (node < n_nodes) {
                float2 acc = __half22float2(*(const __half2*)(hin + (size_t)node * 64 + c0)); // self
                int j = g_rowptr[node];
                const int jend = g_rowptr[node + 1];
                #pragma unroll 1
                for (; j + 8 <= jend; j += 8) {
                    int s[8];
                    #pragma unroll
                    for (int q = 0; q < 8; q++) s[q] = g_col[j + q];
                    __half2 v[8];
                    #pragma unroll
                    for (int q = 0; q < 8; q++)
                        v[q] = *(const __half2*)(hin + (size_t)s[q] * 64 + c0);
                    float2 f0 = __half22float2(v[0]), f1 = __half22float2(v[1]);
                    float2 f2 = __half22float2(v[2]), f3 = __half22float2(v[3]);
                    float2 f4 = __half22float2(v[4]), f5 = __half22float2(v[5]);
                    float2 f6 = __half22float2(v[6]), f7 = __half22float2(v[7]);
                    acc.x += ((f0.x + f1.x) + (f2.x + f3.x)) + ((f4.x + f5.x) + (f6.x + f7.x));
                    acc.y += ((f0.y + f1.y) + (f2.y + f3.y)) + ((f4.y + f5.y) + (f6.y + f7.y));
                }
                for (; j < jend; j++) {
                    float2 v = __half22float2(*(const __half2*)(hin + (size_t)g_col[j] * 64 + c0));
                    acc.x += v.x; acc.y += v.y;
                }
                sh_t[swz(c0, m)] = acc.x;
                sh_t[swz(c1, m)] = acc.y;
            }
        }
        __syncthreads();

        // ---- phase 2a: U = relu(T^T W1 + b1), register-blocked ----
        float a00=0,a01=0,a02=0,a03=0, a10=0,a11=0,a12=0,a13=0;
        float a20=0,a21=0,a22=0,a23=0, a30=0,a31=0,a32=0,a33=0;
        #pragma unroll 8
        for (int k = 0; k < 64; k++) {
            const float4 a = *(const float4*)(sh_t + k * 64 + (ng4 ^ ((k & 15) << 2)));
            const float4 w = *(const float4*)(W1s + k * 64 + cg4);
            a00 = fmaf(w.x, a.x, a00); a01 = fmaf(w.x, a.y, a01); a02 = fmaf(w.x, a.z, a02); a03 = fmaf(w.x, a.w, a03);
            a10 = fmaf(w.y, a.x, a10); a11 = fmaf(w.y, a.y, a11); a12 = fmaf(w.y, a.z, a12); a13 = fmaf(w.y, a.w, a13);
            a20 = fmaf(w.z, a.x, a20); a21 = fmaf(w.z, a.y, a21); a22 = fmaf(w.z, a.z, a22); a23 = fmaf(w.z, a.w, a23);
            a30 = fmaf(w.w, a.x, a30); a31 = fmaf(w.w, a.y, a31); a32 = fmaf(w.w, a.z, a32); a33 = fmaf(w.w, a.w, a33);
        }
        a00 = fmaxf(a00 + b1r[0], 0.f); a01 = fmaxf(a01 + b1r[0], 0.f); a02 = fmaxf(a02 + b1r[0], 0.f); a03 = fmaxf(a03 + b1r[0], 0.f);
        a10 = fmaxf(a10 + b1r[1], 0.f); a11 = fmaxf(a11 + b1r[1], 0.f); a12 = fmaxf(a12 + b1r[1], 0.f); a13 = fmaxf(a13 + b1r[1], 0.f);
        a20 = fmaxf(a20 + b1r[2], 0.f); a21 = fmaxf(a21 + b1r[2], 0.f); a22 = fmaxf(a22 + b1r[2], 0.f); a23 = fmaxf(a23 + b1r[2], 0.f);
        a30 = fmaxf(a30 + b1r[3], 0.f); a31 = fmaxf(a31 + b1r[3], 0.f); a32 = fmaxf(a32 + b1r[3], 0.f); a33 = fmaxf(a33 + b1r[3], 0.f);

        __syncthreads();
        {
            int k0 = cg4;
            *(float4*)(sh_t + (k0 + 0) * 64 + (ng4 ^ (((k0 + 0) & 15) << 2))) = make_float4(a00, a01, a02, a03);
            *(float4*)(sh_t + (k0 + 1) * 64 + (ng4 ^ (((k0 + 1) & 15) << 2))) = make_float4(a10, a11, a12, a13);
            *(float4*)(sh_t + (k0 + 2) * 64 + (ng4 ^ (((k0 + 2) & 15) << 2))) = make_float4(a20, a21, a22, a23);
            *(float4*)(sh_t + (k0 + 3) * 64 + (ng4 ^ (((k0 + 3) & 15) << 2))) = make_float4(a30, a31, a32, a33);
        }
        __syncthreads();

        // ---- phase 2b: V = relu(gamma*(U^T W2 + b2) + beta) ----
        float v00=0,v01=0,v02=0,v03=0, v10=0,v11=0,v12=0,v13=0;
        float v20=0,v21=0,v22=0,v23=0, v30=0,v31=0,v32=0,v33=0;
        #pragma unroll 8
        for (int k = 0; k < 64; k++) {
            const float4 a = *(const float4*)(sh_t + k * 64 + (ng4 ^ ((k & 15) << 2)));
            const float4 w = *(const float4*)(W2s + k * 64 + cg4);
            v00 = fmaf(w.x, a.x, v00); v01 = fmaf(w.x, a.y, v01); v02 = fmaf(w.x, a.z, v02); v03 = fmaf(w.x, a.w, v03);
            v10 = fmaf(w.y, a.x, v10); v11 = fmaf(w.y, a.y, v11); v12 = fmaf(w.y, a.z, v12); v13 = fmaf(w.y, a.w, v13);
            v20 = fmaf(w.z, a.x, v20); v21 = fmaf(w.z, a.y, v21); v22 = fmaf(w.z, a.z, v22); v23 = fmaf(w.z, a.w, v23);
            v30 = fmaf(w.w, a.x, v30); v31 = fmaf(w.w, a.y, v31); v32 = fmaf(w.w, a.z, v32); v33 = fmaf(w.w, a.w, v33);
        }
        #define BNR(v, i) fmaxf(fmaf((v) + b2r[i], gr[i], br[i]), 0.f)
        v00 = BNR(v00, 0); v01 = BNR(v01, 0); v02 = BNR(v02, 0); v03 = BNR(v03, 0);
        v10 = BNR(v10, 1); v11 = BNR(v11, 1); v12 = BNR(v12, 1); v13 = BNR(v13, 1);
        v20 = BNR(v20, 2); v21 = BNR(v21, 2); v22 = BNR(v22, 2); v23 = BNR(v23, 2);
        v30 = BNR(v30, 3); v31 = BNR(v31, 3); v32 = BNR(v32, 3); v33 = BNR(v33, 3);
        #undef BNR

        // ---- store: register transpose -> hout[node][cg4..cg4+3] as half ----
        {
            int n0 = base + ng4;
            if (n0 + 0 < n_nodes) {
                __half2* d = (__half2*)(hout + (size_t)(n0 + 0) * 64 + cg4);
                d[0] = __floats2half2_rn(v00, v10); d[1] = __floats2half2_rn(v20, v30);
            }
            if (n0 + 1 < n_nodes) {
                __half2* d = (__half2*)(hout + (size_t)(n0 + 1) * 64 + cg4);
                d[0] = __floats2half2_rn(v01, v11); d[1] = __floats2half2_rn(v21, v31);
            }
            if (n0 + 2 < n_nodes) {
                __half2* d = (__half2*)(hout + (size_t)(n0 + 2) * 64 + cg4);
                d[0] = __floats2half2_rn(v02, v12); d[1] = __floats2half2_rn(v22, v32);
            }
            if (n0 + 3 < n_nodes) {
                __half2* d = (__half2*)(hout + (size_t)(n0 + 3) * 64 + cg4);
                d[0] = __floats2half2_rn(v03, v13); d[1] = __floats2half2_rn(v23, v33);
            }
        }
        __syncthreads();
    }
}

// ---------------------------------------------------------------------------
__device__ __forceinline__ int lower_bound_i(const int* a, int n, int key) {
    int lo = 0, hi = n;
    while (lo < hi) {
        int mid = (lo + hi) >> 1;
        if (a[mid] < key) lo = mid + 1; else hi = mid;
    }
    return lo;
}

__global__ void pool_kernel(const int* __restrict__ batch, int n_nodes) {
    const __half* __restrict__ h = g_hB;  // final layer output lives in g_hB
    const int g = blockIdx.x;             // 128 blocks, 256 threads
    const int lo = lower_bound_i(batch, n_nodes, g);
    const int hi = lower_bound_i(batch, n_nodes, g + 1);
    const int c = threadIdx.x & 63;
    const int r = threadIdx.x >> 6;       // 4 node-lanes
    float acc = 0.f;
    for (int i = lo + r; i < hi; i += 4) acc += __half2float(h[(size_t)i * 64 + c]);
    __shared__ float sh[256];
    sh[threadIdx.x] = acc;
    __syncthreads();
    if (threadIdx.x < 128) sh[threadIdx.x] += sh[threadIdx.x + 128];
    __syncthreads();
    if (threadIdx.x < 64) {
        float s = sh[threadIdx.x] + sh[threadIdx.x + 64];
        float cnt = (float)(hi - lo);
        g_pooled[g * 64 + threadIdx.x] = s / fmaxf(cnt, 1.f);
    }
}

__global__ void head_kernel(const float* __restrict__ fc1W, const float* __restrict__ fc1b,
                            const float* __restrict__ fc2W, const float* __restrict__ fc2b,
                            float* __restrict__ out, int G) {
    int g = blockIdx.x * blockDim.x + threadIdx.x;
    if (g >= G) return;
    float p[64];
    #pragma unroll
    for (int k = 0; k < 64; k++) p[k] = g_pooled[g * 64 + k];
    float o = fc2b[0];
    for (int j = 0; j < 32; j++) {
        float a = fc1b[j];
        #pragma unroll
        for (int k = 0; k < 64; k++) a = fmaf(p[k], fc1W[k * 32 + j], a);
        o = fmaf(fmaxf(a, 0.f), fc2W[j], o);
    }
    out[g] = o;
}

// ---------------------------------------------------------------------------
extern "C" void kernel_launch(void* const* d_in, const int* in_sizes, int n_in,
                              void* d_out, int out_size) {
    const float* x     = (const float*)d_in[0];
    const int*   ei    = (const int*)d_in[1];     // int32 edge_index [2, E]
    const int*   batch = (const int*)d_in[2];     // int32, sorted
    const float* W1    = (const float*)d_in[3];
    const float* b1    = (const float*)d_in[4];
    const float* W2    = (const float*)d_in[5];
    const float* b2    = (const float*)d_in[6];
    const float* gamma = (const float*)d_in[7];
    const float* beta  = (const float*)d_in[8];
    const float* fc1W  = (const float*)d_in[9];
    const float* fc1b  = (const float*)d_in[10];
    const float* fc2W  = (const float*)d_in[11];
    const float* fc2b  = (const float*)d_in[12];
    float*       out   = (float*)d_out;

    const int N = in_sizes[0] / 64;
    const int E = in_sizes[1] / 2;
    const int G = out_size;
    const int NB = (N + SCB - 1) / SCB;           // scan blocks (98 for N=100000)

    // --- CSR build (dst -> src) + x -> half conversion ---
    zero_deg_kernel<<<(N + 255) / 256, 256>>>(N);
    cvt_kernel<<<(N * 64 / 4 + 255) / 256, 256>>>(x, N * 64);
    hist_kernel<<<1024, 256>>>(ei, E);
    bsum_kernel<<<NB, SCB>>>(N);
    bscan_kernel<<<1, 1024>>>(NB, N);
    scatter_scan_kernel<<<NB, SCB>>>(N);
    fill_kernel<<<1024, 256>>>(ei, E);

    // --- 3 fused GIN layers, ping-pong: A -> B -> A -> B ---
    const int LBLOCKS = 592;   // 4 blocks/SM resident, grid-stride over tiles
    layer_kernel<<<LBLOCKS, 256>>>(1, 2,
                                   W1 + 0 * 4096, b1 + 0 * 64, W2 + 0 * 4096, b2 + 0 * 64,
                                   gamma + 0 * 64, beta + 0 * 64, N);
    layer_kernel<<<LBLOCKS, 256>>>(2, 1,
                                   W1 + 1 * 4096, b1 + 1 * 64, W2 + 1 * 4096, b2 + 1 * 64,
                                   gamma + 1 * 64, beta + 1 * 64, N);
    layer_kernel<<<LBLOCKS, 256>>>(1, 2,
                                   W1 + 2 * 4096, b1 + 2 * 64, W2 + 2 * 4096, b2 + 2 * 64,
                                   gamma + 2 * 64, beta + 2 * 64, N);

    // --- mean pool + head ---
    pool_kernel<<<G, 256>>>(batch, N);
    head_kernel<<<1, 128>>>(fc1W, fc1b, fc2W, fc2b, out, G);
}

// round 8
// speedup vs baseline: 1.7151x; 1.4665x over previous
#include <cuda_runtime.h>
#include <cuda_fp16.h>
#include <cstdint>

// ---------------------------------------------------------------------------
// GIN regression: 3x (scatter-add agg + MLP(64->64->64) + BN-affine + ReLU),
// then per-graph mean pool + 2-layer head -> [128].
//
// FP16 node features (halves gather traffic). MLP on tensor cores:
// mma.sync.m16n8k16 fp16 x fp16 -> fp32 accum. Weights fp16, transposed in
// shared ([n][k], stride 72 halves -> conflict-free fragment loads).
// ---------------------------------------------------------------------------

#define NMAX 100000
#define EMAX 1600000
#define GMAX 128
#define TILE 64          // nodes per block tile
#define SCB  1024        // scan chunk
#define RS   72          // shared tile row stride in halves (pad 64 -> 72)

// scratch (device globals: allocation-free)
__device__ __half g_hA[(size_t)NMAX * 64];
__device__ __half g_hB[(size_t)NMAX * 64];
__device__ int    g_deg[NMAX];
__device__ int    g_rowptr[NMAX + 1];
__device__ int    g_cursor[NMAX];
__device__ int    g_col[EMAX];
__device__ int    g_bsum[128];
__device__ int    g_boff[128];
__device__ float  g_pooled[GMAX * 64];

// ---------------------------------------------------------------------------
__global__ void zero_deg_kernel(int n) {
    int i = blockIdx.x * blockDim.x + threadIdx.x;
    if (i < n) g_deg[i] = 0;
}

__global__ void cvt_kernel(const float* __restrict__ x, int n64) {
    int i = (blockIdx.x * blockDim.x + threadIdx.x) * 4;
    if (i < n64) {
        float4 f = *(const float4*)(x + i);
        *(__half2*)(g_hA + i)     = __floats2half2_rn(f.x, f.y);
        *(__half2*)(g_hA + i + 2) = __floats2half2_rn(f.z, f.w);
    }
}

__global__ void hist_kernel(const int* __restrict__ ei, int E) {
    const int2* dst2 = (const int2*)(ei + E);
    const int E2 = E >> 1;
    for (int e = blockIdx.x * blockDim.x + threadIdx.x; e < E2; e += gridDim.x * blockDim.x) {
        int2 d = dst2[e];
        atomicAdd(&g_deg[d.x], 1);
        atomicAdd(&g_deg[d.y], 1);
    }
}

__global__ void bsum_kernel(int n) {
    __shared__ int sh[32];
    int i = blockIdx.x * SCB + threadIdx.x;
    int v = (i < n) ? g_deg[i] : 0;
    #pragma unroll
    for (int o = 16; o > 0; o >>= 1) v += __shfl_down_sync(0xffffffffu, v, o);
    if ((threadIdx.x & 31) == 0) sh[threadIdx.x >> 5] = v;
    __syncthreads();
    if (threadIdx.x < 32) {
        int w = sh[threadIdx.x];
        #pragma unroll
        for (int o = 16; o > 0; o >>= 1) w += __shfl_down_sync(0xffffffffu, w, o);
        if (threadIdx.x == 0) g_bsum[blockIdx.x] = w;
    }
}

__global__ void bscan_kernel(int nb, int n) {   // 1 block, 1024 threads
    __shared__ int wsum[32];
    const int tid = threadIdx.x, lane = tid & 31, wid = tid >> 5;
    int v = (tid < nb) ? g_bsum[tid] : 0;
    int x = v;
    #pragma unroll
    for (int o = 1; o < 32; o <<= 1) {
        int y = __shfl_up_sync(0xffffffffu, x, o);
        if (lane >= o) x += y;
    }
    if (lane == 31) wsum[wid] = x;
    __syncthreads();
    if (wid == 0) {
        int w = wsum[lane];
        #pragma unroll
        for (int o = 1; o < 32; o <<= 1) {
            int y = __shfl_up_sync(0xffffffffu, w, o);
            if (lane >= o) w += y;
        }
        wsum[lane] = w;
    }
    __syncthreads();
    int excl = x - v + (wid > 0 ? wsum[wid - 1] : 0);
    if (tid < nb) g_boff[tid] = excl;
    if (tid == nb - 1) g_rowptr[n] = excl + v;   // == E
}

__global__ void scatter_scan_kernel(int n) {
    __shared__ int wsum[32];
    const int tid = threadIdx.x, lane = tid & 31, wid = tid >> 5;
    int i = blockIdx.x * SCB + tid;
    int v = (i < n) ? g_deg[i] : 0;
    int x = v;
    #pragma unroll
    for (int o = 1; o < 32; o <<= 1) {
        int y = __shfl_up_sync(0xffffffffu, x, o);
        if (lane >= o) x += y;
    }
    if (lane == 31) wsum[wid] = x;
    __syncthreads();
    if (wid == 0) {
        int w = wsum[lane];
        #pragma unroll
        for (int o = 1; o < 32; o <<= 1) {
            int y = __shfl_up_sync(0xffffffffu, w, o);
            if (lane >= o) w += y;
        }
        wsum[lane] = w;
    }
    __syncthreads();
    int excl = x - v + (wid > 0 ? wsum[wid - 1] : 0) + g_boff[blockIdx.x];
    if (i < n) { g_rowptr[i] = excl; g_cursor[i] = excl; }
}

__global__ void fill_kernel(const int* __restrict__ ei, int E) {
    const int2* src2 = (const int2*)ei;
    const int2* dst2 = (const int2*)(ei + E);
    const int E2 = E >> 1;
    for (int e = blockIdx.x * blockDim.x + threadIdx.x; e < E2; e += gridDim.x * blockDim.x) {
        int2 s = src2[e];
        int2 d = dst2[e];
        int p0 = atomicAdd(&g_cursor[d.x], 1);
        g_col[p0] = s.x;
        int p1 = atomicAdd(&g_cursor[d.y], 1);
        g_col[p1] = s.y;
    }
}

// ---------------------------------------------------------------------------
__device__ __forceinline__ void mma_16x8x16(float& c0, float& c1, float& c2, float& c3,
                                            uint32_t a0, uint32_t a1, uint32_t a2, uint32_t a3,
                                            uint32_t b0, uint32_t b1) {
    asm volatile(
        "mma.sync.aligned.m16n8k16.row.col.f32.f16.f16.f32 "
        "{%0,%1,%2,%3}, {%4,%5,%6,%7}, {%8,%9}, {%0,%1,%2,%3};"
        : "+f"(c0), "+f"(c1), "+f"(c2), "+f"(c3)
        : "r"(a0), "r"(a1), "r"(a2), "r"(a3), "r"(b0), "r"(b1));
}

__global__ __launch_bounds__(256, 4) void layer_kernel(
    int in_sel, int out_sel,
    const float* __restrict__ W1, const float* __restrict__ b1,
    const float* __restrict__ W2, const float* __restrict__ b2,
    const float* __restrict__ gamma, const float* __restrict__ beta,
    int n_nodes)
{
    const __half* __restrict__ hin  = (in_sel == 1) ? g_hA : g_hB;
    __half* __restrict__       hout = (out_sel == 1) ? g_hA : g_hB;

    __shared__ __align__(16) __half W1h[64 * RS];  // [n][k] transposed, fp16
    __shared__ __align__(16) __half W2h[64 * RS];
    __shared__ __align__(16) __half AT[64 * RS];   // agg tile [m][k]
    __shared__ __align__(16) __half UT[64 * RS];   // hidden tile [m][k]
    __shared__ float b1s[64], b2s[64], gs[64], bs[64];

    const int tid = threadIdx.x;
    // weights: load W[k][n] coalesced, store transposed fp16 Wh[n][k]
    for (int i = tid; i < 4096; i += 256) {
        int k = i >> 6, n = i & 63;
        W1h[n * RS + k] = __float2half(W1[i]);
        W2h[n * RS + k] = __float2half(W2[i]);
    }
    if (tid < 64) { b1s[tid] = b1[tid]; b2s[tid] = b2[tid]; gs[tid] = gamma[tid]; bs[tid] = beta[tid]; }
    __syncthreads();

    const int warp = tid >> 5, lane = tid & 31;
    const int gid = lane >> 2, tg = lane & 3;   // mma fragment coords
    const int m0 = (warp & 3) * 16;             // warp's output row block
    const int nb = (warp >> 2) * 32;            // warp's output col block
    const int c0 = 2 * lane;                    // gather channel pair

    const int ntiles = (n_nodes + TILE - 1) / TILE;
    for (int tile = blockIdx.x; tile < ntiles; tile += gridDim.x) {
        const int base = tile * TILE;

        // ---- phase 1: gather (warp-per-node, 8 nodes/warp) -> AT[m][k] ----
        #pragma unroll 1
        for (int i = 0; i < 8; i++) {
            const int m = warp * 8 + i;
            const int node = base + m;
            if (node < n_nodes) {
                float2 acc = __half22float2(*(const __half2*)(hin + (size_t)node * 64 + c0)); // self
                int j = g_rowptr[node];
                const int jend = g_rowptr[node + 1];
                #pragma unroll 1
                for (; j + 8 <= jend; j += 8) {
                    int s[8];
                    #pragma unroll
                    for (int q = 0; q < 8; q++) s[q] = g_col[j + q];
                    __half2 v[8];
                    #pragma unroll
                    for (int q = 0; q < 8; q++)
                        v[q] = *(const __half2*)(hin + (size_t)s[q] * 64 + c0);
                    float2 f0 = __half22float2(v[0]), f1 = __half22float2(v[1]);
                    float2 f2 = __half22float2(v[2]), f3 = __half22float2(v[3]);
                    float2 f4 = __half22float2(v[4]), f5 = __half22float2(v[5]);
                    float2 f6 = __half22float2(v[6]), f7 = __half22float2(v[7]);
                    acc.x += ((f0.x + f1.x) + (f2.x + f3.x)) + ((f4.x + f5.x) + (f6.x + f7.x));
                    acc.y += ((f0.y + f1.y) + (f2.y + f3.y)) + ((f4.y + f5.y) + (f6.y + f7.y));
                }
                for (; j < jend; j++) {
                    float2 v = __half22float2(*(const __half2*)(hin + (size_t)g_col[j] * 64 + c0));
                    acc.x += v.x; acc.y += v.y;
                }
                *(__half2*)(AT + m * RS + c0) = __floats2half2_rn(acc.x, acc.y);
            }
        }
        __syncthreads();   // AT complete; also orders prior-tile UT reads

        // ---- phase 2a: U = relu(AT @ W1 + b1) via HMMA ----
        {
            float acc[4][4];
            #pragma unroll
            for (int nf = 0; nf < 4; nf++)
                #pragma unroll
                for (int q = 0; q < 4; q++) acc[nf][q] = 0.f;
            #pragma unroll
            for (int ks = 0; ks < 4; ks++) {
                const int k0 = ks * 16;
                uint32_t a0 = *(const uint32_t*)(AT + (m0 + gid)     * RS + k0 + 2 * tg);
                uint32_t a1 = *(const uint32_t*)(AT + (m0 + gid + 8) * RS + k0 + 2 * tg);
                uint32_t a2 = *(const uint32_t*)(AT + (m0 + gid)     * RS + k0 + 8 + 2 * tg);
                uint32_t a3 = *(const uint32_t*)(AT + (m0 + gid + 8) * RS + k0 + 8 + 2 * tg);
                #pragma unroll
                for (int nf = 0; nf < 4; nf++) {
                    const int n = nb + nf * 8 + gid;
                    uint32_t bb0 = *(const uint32_t*)(W1h + n * RS + k0 + 2 * tg);
                    uint32_t bb1 = *(const uint32_t*)(W1h + n * RS + k0 + 8 + 2 * tg);
                    mma_16x8x16(acc[nf][0], acc[nf][1], acc[nf][2], acc[nf][3],
                                a0, a1, a2, a3, bb0, bb1);
                }
            }
            // epilogue: bias + relu, store fp16 into UT[m][n]
            #pragma unroll
            for (int nf = 0; nf < 4; nf++) {
                const int ncol = nb + nf * 8 + 2 * tg;
                float u0 = fmaxf(acc[nf][0] + b1s[ncol], 0.f);
                float u1 = fmaxf(acc[nf][1] + b1s[ncol + 1], 0.f);
                float u2 = fmaxf(acc[nf][2] + b1s[ncol], 0.f);
                float u3 = fmaxf(acc[nf][3] + b1s[ncol + 1], 0.f);
                *(__half2*)(UT + (m0 + gid)     * RS + ncol) = __floats2half2_rn(u0, u1);
                *(__half2*)(UT + (m0 + gid + 8) * RS + ncol) = __floats2half2_rn(u2, u3);
            }
        }
        __syncthreads();   // UT complete; all AT reads (GEMM1) done

        // ---- phase 2b: V = relu(gamma*(UT @ W2 + b2) + beta) -> hout ----
        {
            float acc[4][4];
            #pragma unroll
            for (int nf = 0; nf < 4; nf++)
                #pragma unroll
                for (int q = 0; q < 4; q++) acc[nf][q] = 0.f;
            #pragma unroll
            for (int ks = 0; ks < 4; ks++) {
                const int k0 = ks * 16;
                uint32_t a0 = *(const uint32_t*)(UT + (m0 + gid)     * RS + k0 + 2 * tg);
                uint32_t a1 = *(const uint32_t*)(UT + (m0 + gid + 8) * RS + k0 + 2 * tg);
                uint32_t a2 = *(const uint32_t*)(UT + (m0 + gid)     * RS + k0 + 8 + 2 * tg);
                uint32_t a3 = *(const uint32_t*)(UT + (m0 + gid + 8) * RS + k0 + 8 + 2 * tg);
                #pragma unroll
                for (int nf = 0; nf < 4; nf++) {
                    const int n = nb + nf * 8 + gid;
                    uint32_t bb0 = *(const uint32_t*)(W2h + n * RS + k0 + 2 * tg);
                    uint32_t bb1 = *(const uint32_t*)(W2h + n * RS + k0 + 8 + 2 * tg);
                    mma_16x8x16(acc[nf][0], acc[nf][1], acc[nf][2], acc[nf][3],
                                a0, a1, a2, a3, bb0, bb1);
                }
            }
            const int row0 = base + m0 + gid;
            const int row1 = row0 + 8;
            #pragma unroll
            for (int nf = 0; nf < 4; nf++) {
                const int ncol = nb + nf * 8 + 2 * tg;
                float v0 = fmaxf(fmaf(acc[nf][0] + b2s[ncol],     gs[ncol],     bs[ncol]),     0.f);
                float v1 = fmaxf(fmaf(acc[nf][1] + b2s[ncol + 1], gs[ncol + 1], bs[ncol + 1]), 0.f);
                float v2 = fmaxf(fmaf(acc[nf][2] + b2s[ncol],     gs[ncol],     bs[ncol]),     0.f);
                float v3 = fmaxf(fmaf(acc[nf][3] + b2s[ncol + 1], gs[ncol + 1], bs[ncol + 1]), 0.f);
                if (row0 < n_nodes)
                    *(__half2*)(hout + (size_t)row0 * 64 + ncol) = __floats2half2_rn(v0, v1);
                if (row1 < n_nodes)
                    *(__half2*)(hout + (size_t)row1 * 64 + ncol) = __floats2half2_rn(v2, v3);
            }
        }
        // no sync needed here: next-tile AT writes are ordered by the post-
        // gather sync (every warp reaches it only after finishing GEMM2).
    }
}

// ---------------------------------------------------------------------------
__device__ __forceinline__ int lower_bound_i(const int* a, int n, int key) {
    int lo = 0, hi = n;
    while (lo < hi) {
        int mid = (lo + hi) >> 1;
        if (a[mid] < key) lo = mid + 1; else hi = mid;
    }
    return lo;
}

__global__ void pool_kernel(const int* __restrict__ batch, int n_nodes) {
    const __half* __restrict__ h = g_hB;  // final layer output lives in g_hB
    const int g = blockIdx.x;
    const int lo = lower_bound_i(batch, n_nodes, g);
    const int hi = lower_bound_i(batch, n_nodes, g + 1);
    const int c = threadIdx.x & 63;
    const int r = threadIdx.x >> 6;
    float acc = 0.f;
    for (int i = lo + r; i < hi; i += 4) acc += __half2float(h[(size_t)i * 64 + c]);
    __shared__ float sh[256];
    sh[threadIdx.x] = acc;
    __syncthreads();
    if (threadIdx.x < 128) sh[threadIdx.x] += sh[threadIdx.x + 128];
    __syncthreads();
    if (threadIdx.x < 64) {
        float s = sh[threadIdx.x] + sh[threadIdx.x + 64];
        float cnt = (float)(hi - lo);
        g_pooled[g * 64 + threadIdx.x] = s / fmaxf(cnt, 1.f);
    }
}

__global__ void head_kernel(const float* __restrict__ fc1W, const float* __restrict__ fc1b,
                            const float* __restrict__ fc2W, const float* __restrict__ fc2b,
                            float* __restrict__ out, int G) {
    int g = blockIdx.x * blockDim.x + threadIdx.x;
    if (g >= G) return;
    float p[64];
    #pragma unroll
    for (int k = 0; k < 64; k++) p[k] = g_pooled[g * 64 + k];
    float o = fc2b[0];
    for (int j = 0; j < 32; j++) {
        float a = fc1b[j];
        #pragma unroll
        for (int k = 0; k < 64; k++) a = fmaf(p[k], fc1W[k * 32 + j], a);
        o = fmaf(fmaxf(a, 0.f), fc2W[j], o);
    }
    out[g] = o;
}

// ---------------------------------------------------------------------------
extern "C" void kernel_launch(void* const* d_in, const int* in_sizes, int n_in,
                              void* d_out, int out_size) {
    const float* x     = (const float*)d_in[0];
    const int*   ei    = (const int*)d_in[1];
    const int*   batch = (const int*)d_in[2];
    const float* W1    = (const float*)d_in[3];
    const float* b1    = (const float*)d_in[4];
    const float* W2    = (const float*)d_in[5];
    const float* b2    = (const float*)d_in[6];
    const float* gamma = (const float*)d_in[7];
    const float* beta  = (const float*)d_in[8];
    const float* fc1W  = (const float*)d_in[9];
    const float* fc1b  = (const float*)d_in[10];
    const float* fc2W  = (const float*)d_in[11];
    const float* fc2b  = (const float*)d_in[12];
    float*       out   = (float*)d_out;

    const int N = in_sizes[0] / 64;
    const int E = in_sizes[1] / 2;
    const int G = out_size;
    const int NB = (N + SCB - 1) / SCB;

    // --- CSR build (dst -> src) + x -> half conversion ---
    zero_deg_kernel<<<(N + 255) / 256, 256>>>(N);
    cvt_kernel<<<(N * 64 / 4 + 255) / 256, 256>>>(x, N * 64);
    hist_kernel<<<1024, 256>>>(ei, E);
    bsum_kernel<<<NB, SCB>>>(N);
    bscan_kernel<<<1, 1024>>>(NB, N);
    scatter_scan_kernel<<<NB, SCB>>>(N);
    fill_kernel<<<1024, 256>>>(ei, E);

    // --- 3 fused GIN layers, ping-pong: A -> B -> A -> B ---
    const int LBLOCKS = 592;
    layer_kernel<<<LBLOCKS, 256>>>(1, 2,
                                   W1 + 0 * 4096, b1 + 0 * 64, W2 + 0 * 4096, b2 + 0 * 64,
                                   gamma + 0 * 64, beta + 0 * 64, N);
    layer_kernel<<<LBLOCKS, 256>>>(2, 1,
                                   W1 + 1 * 4096, b1 + 1 * 64, W2 + 1 * 4096, b2 + 1 * 64,
                                   gamma + 1 * 64, beta + 1 * 64, N);
    layer_kernel<<<LBLOCKS, 256>>>(1, 2,
                                   W1 + 2 * 4096, b1 + 2 * 64, W2 + 2 * 4096, b2 + 2 * 64,
                                   gamma + 2 * 64, beta + 2 * 64, N);

    // --- mean pool + head ---
    pool_kernel<<<G, 256>>>(batch, N);
    head_kernel<<<1, 128>>>(fc1W, fc1b, fc2W, fc2b, out, G);
}

// round 9
// speedup vs baseline: 1.7621x; 1.0274x over previous
#include <cuda_runtime.h>
#include <cuda_fp16.h>
#include <cstdint>

// ---------------------------------------------------------------------------
// GIN regression: 3x (scatter-add agg + MLP(64->64->64) + BN-affine + ReLU),
// then per-graph mean pool + 2-layer head -> [128].
//
// FP16 node features (halves gather traffic). MLP on tensor cores
// (mma.sync.m16n8k16 f16f16f32). Dynamic work-queue tile scheduler: blocks
// pop tiles from a global atomic counter -> no grid-stride tail imbalance.
// ---------------------------------------------------------------------------

#define NMAX 100000
#define EMAX 1600000
#define GMAX 128
#define TILE 64          // nodes per block tile
#define SCB  1024        // scan chunk
#define RS   72          // shared tile row stride in halves (pad 64 -> 72)

// scratch (device globals: allocation-free)
__device__ __half g_hA[(size_t)NMAX * 64];
__device__ __half g_hB[(size_t)NMAX * 64];
__device__ int    g_deg[NMAX];
__device__ int    g_rowptr[NMAX + 1];
__device__ int    g_cursor[NMAX];
__device__ int    g_col[EMAX];
__device__ int    g_bsum[128];
__device__ int    g_boff[128];
__device__ int    g_tilectr[3];
__device__ float  g_pooled[GMAX * 64];

// ---------------------------------------------------------------------------
__global__ void zero_deg_kernel(int n) {
    int i = blockIdx.x * blockDim.x + threadIdx.x;
    if (i < n) g_deg[i] = 0;
    if (i < 3) g_tilectr[i] = 0;
}

__global__ void cvt_kernel(const float* __restrict__ x, int n64) {
    int i = (blockIdx.x * blockDim.x + threadIdx.x) * 4;
    if (i < n64) {
        float4 f = *(const float4*)(x + i);
        *(__half2*)(g_hA + i)     = __floats2half2_rn(f.x, f.y);
        *(__half2*)(g_hA + i + 2) = __floats2half2_rn(f.z, f.w);
    }
}

__global__ void hist_kernel(const int* __restrict__ ei, int E) {
    const int2* dst2 = (const int2*)(ei + E);
    const int E2 = E >> 1;
    for (int e = blockIdx.x * blockDim.x + threadIdx.x; e < E2; e += gridDim.x * blockDim.x) {
        int2 d = dst2[e];
        atomicAdd(&g_deg[d.x], 1);
        atomicAdd(&g_deg[d.y], 1);
    }
}

__global__ void bsum_kernel(int n) {
    __shared__ int sh[32];
    int i = blockIdx.x * SCB + threadIdx.x;
    int v = (i < n) ? g_deg[i] : 0;
    #pragma unroll
    for (int o = 16; o > 0; o >>= 1) v += __shfl_down_sync(0xffffffffu, v, o);
    if ((threadIdx.x & 31) == 0) sh[threadIdx.x >> 5] = v;
    __syncthreads();
    if (threadIdx.x < 32) {
        int w = sh[threadIdx.x];
        #pragma unroll
        for (int o = 16; o > 0; o >>= 1) w += __shfl_down_sync(0xffffffffu, w, o);
        if (threadIdx.x == 0) g_bsum[blockIdx.x] = w;
    }
}

__global__ void bscan_kernel(int nb, int n) {   // 1 block, 1024 threads
    __shared__ int wsum[32];
    const int tid = threadIdx.x, lane = tid & 31, wid = tid >> 5;
    int v = (tid < nb) ? g_bsum[tid] : 0;
    int x = v;
    #pragma unroll
    for (int o = 1; o < 32; o <<= 1) {
        int y = __shfl_up_sync(0xffffffffu, x, o);
        if (lane >= o) x += y;
    }
    if (lane == 31) wsum[wid] = x;
    __syncthreads();
    if (wid == 0) {
        int w = wsum[lane];
        #pragma unroll
        for (int o = 1; o < 32; o <<= 1) {
            int y = __shfl_up_sync(0xffffffffu, w, o);
            if (lane >= o) w += y;
        }
        wsum[lane] = w;
    }
    __syncthreads();
    int excl = x - v + (wid > 0 ? wsum[wid - 1] : 0);
    if (tid < nb) g_boff[tid] = excl;
    if (tid == nb - 1) g_rowptr[n] = excl + v;   // == E
}

__global__ void scatter_scan_kernel(int n) {
    __shared__ int wsum[32];
    const int tid = threadIdx.x, lane = tid & 31, wid = tid >> 5;
    int i = blockIdx.x * SCB + tid;
    int v = (i < n) ? g_deg[i] : 0;
    int x = v;
    #pragma unroll
    for (int o = 1; o < 32; o <<= 1) {
        int y = __shfl_up_sync(0xffffffffu, x, o);
        if (lane >= o) x += y;
    }
    if (lane == 31) wsum[wid] = x;
    __syncthreads();
    if (wid == 0) {
        int w = wsum[lane];
        #pragma unroll
        for (int o = 1; o < 32; o <<= 1) {
            int y = __shfl_up_sync(0xffffffffu, w, o);
            if (lane >= o) w += y;
        }
        wsum[lane] = w;
    }
    __syncthreads();
    int excl = x - v + (wid > 0 ? wsum[wid - 1] : 0) + g_boff[blockIdx.x];
    if (i < n) { g_rowptr[i] = excl; g_cursor[i] = excl; }
}

__global__ void fill_kernel(const int* __restrict__ ei, int E) {
    const int2* src2 = (const int2*)ei;
    const int2* dst2 = (const int2*)(ei + E);
    const int E2 = E >> 1;
    for (int e = blockIdx.x * blockDim.x + threadIdx.x; e < E2; e += gridDim.x * blockDim.x) {
        int2 s = src2[e];
        int2 d = dst2[e];
        int p0 = atomicAdd(&g_cursor[d.x], 1);
        g_col[p0] = s.x;
        int p1 = atomicAdd(&g_cursor[d.y], 1);
        g_col[p1] = s.y;
    }
}

// ---------------------------------------------------------------------------
__device__ __forceinline__ void mma_16x8x16(float& c0, float& c1, float& c2, float& c3,
                                            uint32_t a0, uint32_t a1, uint32_t a2, uint32_t a3,
                                            uint32_t b0, uint32_t b1) {
    asm volatile(
        "mma.sync.aligned.m16n8k16.row.col.f32.f16.f16.f32 "
        "{%0,%1,%2,%3}, {%4,%5,%6,%7}, {%8,%9}, {%0,%1,%2,%3};"
        : "+f"(c0), "+f"(c1), "+f"(c2), "+f"(c3)
        : "r"(a0), "r"(a1), "r"(a2), "r"(a3), "r"(b0), "r"(b1));
}

__global__ __launch_bounds__(256, 4) void layer_kernel(
    int in_sel, int out_sel, int layer_idx,
    const float* __restrict__ W1, const float* __restrict__ b1,
    const float* __restrict__ W2, const float* __restrict__ b2,
    const float* __restrict__ gamma, const float* __restrict__ beta,
    int n_nodes)
{
    const __half* __restrict__ hin  = (in_sel == 1) ? g_hA : g_hB;
    __half* __restrict__       hout = (out_sel == 1) ? g_hA : g_hB;

    __shared__ __align__(16) __half W1h[64 * RS];  // [n][k] transposed, fp16
    __shared__ __align__(16) __half W2h[64 * RS];
    __shared__ __align__(16) __half AT[64 * RS];   // agg tile [m][k]
    __shared__ __align__(16) __half UT[64 * RS];   // hidden tile [m][k]
    __shared__ float b1s[64], b2s[64], gs[64], bs[64];
    __shared__ int s_tile;

    const int tid = threadIdx.x;
    // weights: load W[k][n] coalesced, store transposed fp16 Wh[n][k]
    for (int i = tid; i < 4096; i += 256) {
        int k = i >> 6, n = i & 63;
        W1h[n * RS + k] = __float2half(W1[i]);
        W2h[n * RS + k] = __float2half(W2[i]);
    }
    if (tid < 64) { b1s[tid] = b1[tid]; b2s[tid] = b2[tid]; gs[tid] = gamma[tid]; bs[tid] = beta[tid]; }

    const int warp = tid >> 5, lane = tid & 31;
    const int gid = lane >> 2, tg = lane & 3;   // mma fragment coords
    const int m0 = (warp & 3) * 16;             // warp's output row block
    const int nb = (warp >> 2) * 32;            // warp's output col block
    const int c0 = 2 * lane;                    // gather channel pair

    const int ntiles = (n_nodes + TILE - 1) / TILE;
    for (;;) {
        if (tid == 0) s_tile = atomicAdd(&g_tilectr[layer_idx], 1);
        __syncthreads();                         // s_tile ready (+ weights on 1st iter)
        const int tile = s_tile;
        if (tile >= ntiles) break;
        const int base = tile * TILE;

        // ---- phase 1: gather (warp-per-node, 8 nodes/warp) -> AT[m][k] ----
        #pragma unroll 1
        for (int i = 0; i < 8; i++) {
            const int m = warp * 8 + i;
            const int node = base + m;
            if (node < n_nodes) {
                float2 acc = __half22float2(*(const __half2*)(hin + (size_t)node * 64 + c0)); // self
                int j = g_rowptr[node];
                const int jend = g_rowptr[node + 1];
                #pragma unroll 1
                for (; j + 8 <= jend; j += 8) {
                    int s[8];
                    #pragma unroll
                    for (int q = 0; q < 8; q++) s[q] = g_col[j + q];
                    __half2 v[8];
                    #pragma unroll
                    for (int q = 0; q < 8; q++)
                        v[q] = *(const __half2*)(hin + (size_t)s[q] * 64 + c0);
                    float2 f0 = __half22float2(v[0]), f1 = __half22float2(v[1]);
                    float2 f2 = __half22float2(v[2]), f3 = __half22float2(v[3]);
                    float2 f4 = __half22float2(v[4]), f5 = __half22float2(v[5]);
                    float2 f6 = __half22float2(v[6]), f7 = __half22float2(v[7]);
                    acc.x += ((f0.x + f1.x) + (f2.x + f3.x)) + ((f4.x + f5.x) + (f6.x + f7.x));
                    acc.y += ((f0.y + f1.y) + (f2.y + f3.y)) + ((f4.y + f5.y) + (f6.y + f7.y));
                }
                for (; j < jend; j++) {
                    float2 v = __half22float2(*(const __half2*)(hin + (size_t)g_col[j] * 64 + c0));
                    acc.x += v.x; acc.y += v.y;
                }
                *(__half2*)(AT + m * RS + c0) = __floats2half2_rn(acc.x, acc.y);
            }
        }
        __syncthreads();   // AT complete

        // ---- phase 2a: U = relu(AT @ W1 + b1) via HMMA ----
        {
            float acc[4][4];
            #pragma unroll
            for (int nf = 0; nf < 4; nf++)
                #pragma unroll
                for (int q = 0; q < 4; q++) acc[nf][q] = 0.f;
            #pragma unroll
            for (int ks = 0; ks < 4; ks++) {
                const int k0 = ks * 16;
                uint32_t a0 = *(const uint32_t*)(AT + (m0 + gid)     * RS + k0 + 2 * tg);
                uint32_t a1 = *(const uint32_t*)(AT + (m0 + gid + 8) * RS + k0 + 2 * tg);
                uint32_t a2 = *(const uint32_t*)(AT + (m0 + gid)     * RS + k0 + 8 + 2 * tg);
                uint32_t a3 = *(const uint32_t*)(AT + (m0 + gid + 8) * RS + k0 + 8 + 2 * tg);
                #pragma unroll
                for (int nf = 0; nf < 4; nf++) {
                    const int n = nb + nf * 8 + gid;
                    uint32_t bb0 = *(const uint32_t*)(W1h + n * RS + k0 + 2 * tg);
                    uint32_t bb1 = *(const uint32_t*)(W1h + n * RS + k0 + 8 + 2 * tg);
                    mma_16x8x16(acc[nf][0], acc[nf][1], acc[nf][2], acc[nf][3],
                                a0, a1, a2, a3, bb0, bb1);
                }
            }
            #pragma unroll
            for (int nf = 0; nf < 4; nf++) {
                const int ncol = nb + nf * 8 + 2 * tg;
                float u0 = fmaxf(acc[nf][0] + b1s[ncol], 0.f);
                float u1 = fmaxf(acc[nf][1] + b1s[ncol + 1], 0.f);
                float u2 = fmaxf(acc[nf][2] + b1s[ncol], 0.f);
                float u3 = fmaxf(acc[nf][3] + b1s[ncol + 1], 0.f);
                *(__half2*)(UT + (m0 + gid)     * RS + ncol) = __floats2half2_rn(u0, u1);
                *(__half2*)(UT + (m0 + gid + 8) * RS + ncol) = __floats2half2_rn(u2, u3);
            }
        }
        __syncthreads();   // UT complete; all AT reads done

        // ---- phase 2b: V = relu(gamma*(UT @ W2 + b2) + beta) -> hout ----
        {
            float acc[4][4];
            #pragma unroll
            for (int nf = 0; nf < 4; nf++)
                #pragma unroll
                for (int q = 0; q < 4; q++) acc[nf][q] = 0.f;
            #pragma unroll
            for (int ks = 0; ks < 4; ks++) {
                const int k0 = ks * 16;
                uint32_t a0 = *(const uint32_t*)(UT + (m0 + gid)     * RS + k0 + 2 * tg);
                uint32_t a1 = *(const uint32_t*)(UT + (m0 + gid + 8) * RS + k0 + 2 * tg);
                uint32_t a2 = *(const uint32_t*)(UT + (m0 + gid)     * RS + k0 + 8 + 2 * tg);
                uint32_t a3 = *(const uint32_t*)(UT + (m0 + gid + 8) * RS + k0 + 8 + 2 * tg);
                #pragma unroll
                for (int nf = 0; nf < 4; nf++) {
                    const int n = nb + nf * 8 + gid;
                    uint32_t bb0 = *(const uint32_t*)(W2h + n * RS + k0 + 2 * tg);
                    uint32_t bb1 = *(const uint32_t*)(W2h + n * RS + k0 + 8 + 2 * tg);
                    mma_16x8x16(acc[nf][0], acc[nf][1], acc[nf][2], acc[nf][3],
                                a0, a1, a2, a3, bb0, bb1);
                }
            }
            const int row0 = base + m0 + gid;
            const int row1 = row0 + 8;
            #pragma unroll
            for (int nf = 0; nf < 4; nf++) {
                const int ncol = nb + nf * 8 + 2 * tg;
                float v0 = fmaxf(fmaf(acc[nf][0] + b2s[ncol],     gs[ncol],     bs[ncol]),     0.f);
                float v1 = fmaxf(fmaf(acc[nf][1] + b2s[ncol + 1], gs[ncol + 1], bs[ncol + 1]), 0.f);
                float v2 = fmaxf(fmaf(acc[nf][2] + b2s[ncol],     gs[ncol],     bs[ncol]),     0.f);
                float v3 = fmaxf(fmaf(acc[nf][3] + b2s[ncol + 1], gs[ncol + 1], bs[ncol + 1]), 0.f);
                if (row0 < n_nodes)
                    *(__half2*)(hout + (size_t)row0 * 64 + ncol) = __floats2half2_rn(v0, v1);
                if (row1 < n_nodes)
                    *(__half2*)(hout + (size_t)row1 * 64 + ncol) = __floats2half2_rn(v2, v3);
            }
        }
        __syncthreads();   // all UT reads done before next tile's s_tile write
    }
}

// ---------------------------------------------------------------------------
__device__ __forceinline__ int lower_bound_i(const int* a, int n, int key) {
    int lo = 0, hi = n;
    while (lo < hi) {
        int mid = (lo + hi) >> 1;
        if (a[mid] < key) lo = mid + 1; else hi = mid;
    }
    return lo;
}

__global__ void pool_kernel(const int* __restrict__ batch, int n_nodes) {
    const __half* __restrict__ h = g_hB;  // final layer output lives in g_hB
    const int g = blockIdx.x;
    const int lo = lower_bound_i(batch, n_nodes, g);
    const int hi = lower_bound_i(batch, n_nodes, g + 1);
    const int c = threadIdx.x & 63;
    const int r = threadIdx.x >> 6;
    float acc = 0.f;
    for (int i = lo + r; i < hi; i += 4) acc += __half2float(h[(size_t)i * 64 + c]);
    __shared__ float sh[256];
    sh[threadIdx.x] = acc;
    __syncthreads();
    if (threadIdx.x < 128) sh[threadIdx.x] += sh[threadIdx.x + 128];
    __syncthreads();
    if (threadIdx.x < 64) {
        float s = sh[threadIdx.x] + sh[threadIdx.x + 64];
        float cnt = (float)(hi - lo);
        g_pooled[g * 64 + threadIdx.x] = s / fmaxf(cnt, 1.f);
    }
}

__global__ void head_kernel(const float* __restrict__ fc1W, const float* __restrict__ fc1b,
                            const float* __restrict__ fc2W, const float* __restrict__ fc2b,
                            float* __restrict__ out, int G) {
    int g = blockIdx.x * blockDim.x + threadIdx.x;
    if (g >= G) return;
    float p[64];
    #pragma unroll
    for (int k = 0; k < 64; k++) p[k] = g_pooled[g * 64 + k];
    float o = fc2b[0];
    for (int j = 0; j < 32; j++) {
        float a = fc1b[j];
        #pragma unroll
        for (int k = 0; k < 64; k++) a = fmaf(p[k], fc1W[k * 32 + j], a);
        o = fmaf(fmaxf(a, 0.f), fc2W[j], o);
    }
    out[g] = o;
}

// ---------------------------------------------------------------------------
extern "C" void kernel_launch(void* const* d_in, const int* in_sizes, int n_in,
                              void* d_out, int out_size) {
    const float* x     = (const float*)d_in[0];
    const int*   ei    = (const int*)d_in[1];
    const int*   batch = (const int*)d_in[2];
    const float* W1    = (const float*)d_in[3];
    const float* b1    = (const float*)d_in[4];
    const float* W2    = (const float*)d_in[5];
    const float* b2    = (const float*)d_in[6];
    const float* gamma = (const float*)d_in[7];
    const float* beta  = (const float*)d_in[8];
    const float* fc1W  = (const float*)d_in[9];
    const float* fc1b  = (const float*)d_in[10];
    const float* fc2W  = (const float*)d_in[11];
    const float* fc2b  = (const float*)d_in[12];
    float*       out   = (float*)d_out;

    const int N = in_sizes[0] / 64;
    const int E = in_sizes[1] / 2;
    const int G = out_size;
    const int NB = (N + SCB - 1) / SCB;

    // --- CSR build (dst -> src) + x -> half conversion ---
    zero_deg_kernel<<<(N + 255) / 256, 256>>>(N);
    cvt_kernel<<<(N * 64 / 4 + 255) / 256, 256>>>(x, N * 64);
    hist_kernel<<<1024, 256>>>(ei, E);
    bsum_kernel<<<NB, SCB>>>(N);
    bscan_kernel<<<1, 1024>>>(NB, N);
    scatter_scan_kernel<<<NB, SCB>>>(N);
    fill_kernel<<<1024, 256>>>(ei, E);

    // --- 3 fused GIN layers, ping-pong: A -> B -> A -> B ---
    const int LBLOCKS = 592;   // 4 blocks/SM resident; tiles via work queue
    layer_kernel<<<LBLOCKS, 256>>>(1, 2, 0,
                                   W1 + 0 * 4096, b1 + 0 * 64, W2 + 0 * 4096, b2 + 0 * 64,
                                   gamma + 0 * 64, beta + 0 * 64, N);
    layer_kernel<<<LBLOCKS, 256>>>(2, 1, 1,
                                   W1 + 1 * 4096, b1 + 1 * 64, W2 + 1 * 4096, b2 + 1 * 64,
                                   gamma + 1 * 64, beta + 1 * 64, N);
    layer_kernel<<<LBLOCKS, 256>>>(1, 2, 2,
                                   W1 + 2 * 4096, b1 + 2 * 64, W2 + 2 * 4096, b2 + 2 * 64,
                                   gamma + 2 * 64, beta + 2 * 64, N);

    // --- mean pool + head ---
    pool_kernel<<<G, 256>>>(batch, N);
    head_kernel<<<1, 128>>>(fc1W, fc1b, fc2W, fc2b, out, G);
}

// round 10
// speedup vs baseline: 1.9959x; 1.1327x over previous
#include <cuda_runtime.h>
#include <cuda_fp16.h>
#include <cstdint>

// ---------------------------------------------------------------------------
// GIN regression: 3x (scatter-add agg + MLP(64->64->64) + BN-affine + ReLU),
// then per-graph mean pool + 2-layer head -> [128].
//
// FP16 node features, tensor-core MLP (m16n8k16 f16f16f32), dynamic
// work-queue tiles, 5 blocks/SM, fused pool+head.
// ---------------------------------------------------------------------------

#define NMAX 100000
#define EMAX 1600000
#define GMAX 128
#define TILE 64          // nodes per block tile
#define SCB  1024        // scan chunk
#define RS   72          // shared tile row stride in halves (pad 64 -> 72)

// scratch (device globals: allocation-free)
__device__ __half g_hA[(size_t)NMAX * 64];
__device__ __half g_hB[(size_t)NMAX * 64];
__device__ int    g_deg[NMAX];
__device__ int    g_rowptr[NMAX + 1];
__device__ int    g_cursor[NMAX];
__device__ int    g_col[EMAX];
__device__ int    g_bsum[128];
__device__ int    g_boff[128];
__device__ int    g_tilectr[3];

// ---------------------------------------------------------------------------
// fused: zero deg/tilectr + convert x to fp16
__global__ void init_kernel(const float* __restrict__ x, int n_nodes, int n64) {
    int t = blockIdx.x * blockDim.x + threadIdx.x;
    if (t < n_nodes) g_deg[t] = 0;
    if (t < 3) g_tilectr[t] = 0;
    int i = t * 4;
    if (i < n64) {
        float4 f = *(const float4*)(x + i);
        *(__half2*)(g_hA + i)     = __floats2half2_rn(f.x, f.y);
        *(__half2*)(g_hA + i + 2) = __floats2half2_rn(f.z, f.w);
    }
}

__global__ void hist_kernel(const int* __restrict__ ei, int E) {
    const int4* dst4 = (const int4*)(ei + E);     // E divisible by 4 in practice
    const int E4 = E >> 2;
    for (int e = blockIdx.x * blockDim.x + threadIdx.x; e < E4; e += gridDim.x * blockDim.x) {
        int4 d = dst4[e];
        atomicAdd(&g_deg[d.x], 1);
        atomicAdd(&g_deg[d.y], 1);
        atomicAdd(&g_deg[d.z], 1);
        atomicAdd(&g_deg[d.w], 1);
    }
    // tail (E not multiple of 4)
    int tail = E & 3;
    if (blockIdx.x == 0 && threadIdx.x < tail)
        atomicAdd(&g_deg[ei[E + (E & ~3) + threadIdx.x]], 1);
}

__global__ void bsum_kernel(int n) {
    __shared__ int sh[32];
    int i = blockIdx.x * SCB + threadIdx.x;
    int v = (i < n) ? g_deg[i] : 0;
    #pragma unroll
    for (int o = 16; o > 0; o >>= 1) v += __shfl_down_sync(0xffffffffu, v, o);
    if ((threadIdx.x & 31) == 0) sh[threadIdx.x >> 5] = v;
    __syncthreads();
    if (threadIdx.x < 32) {
        int w = sh[threadIdx.x];
        #pragma unroll
        for (int o = 16; o > 0; o >>= 1) w += __shfl_down_sync(0xffffffffu, w, o);
        if (threadIdx.x == 0) g_bsum[blockIdx.x] = w;
    }
}

__global__ void bscan_kernel(int nb, int n) {   // 1 block, 1024 threads
    __shared__ int wsum[32];
    const int tid = threadIdx.x, lane = tid & 31, wid = tid >> 5;
    int v = (tid < nb) ? g_bsum[tid] : 0;
    int x = v;
    #pragma unroll
    for (int o = 1; o < 32; o <<= 1) {
        int y = __shfl_up_sync(0xffffffffu, x, o);
        if (lane >= o) x += y;
    }
    if (lane == 31) wsum[wid] = x;
    __syncthreads();
    if (wid == 0) {
        int w = wsum[lane];
        #pragma unroll
        for (int o = 1; o < 32; o <<= 1) {
            int y = __shfl_up_sync(0xffffffffu, w, o);
            if (lane >= o) w += y;
        }
        wsum[lane] = w;
    }
    __syncthreads();
    int excl = x - v + (wid > 0 ? wsum[wid - 1] : 0);
    if (tid < nb) g_boff[tid] = excl;
    if (tid == nb - 1) g_rowptr[n] = excl + v;   // == E
}

__global__ void scatter_scan_kernel(int n) {
    __shared__ int wsum[32];
    const int tid = threadIdx.x, lane = tid & 31, wid = tid >> 5;
    int i = blockIdx.x * SCB + tid;
    int v = (i < n) ? g_deg[i] : 0;
    int x = v;
    #pragma unroll
    for (int o = 1; o < 32; o <<= 1) {
        int y = __shfl_up_sync(0xffffffffu, x, o);
        if (lane >= o) x += y;
    }
    if (lane == 31) wsum[wid] = x;
    __syncthreads();
    if (wid == 0) {
        int w = wsum[lane];
        #pragma unroll
        for (int o = 1; o < 32; o <<= 1) {
            int y = __shfl_up_sync(0xffffffffu, w, o);
            if (lane >= o) w += y;
        }
        wsum[lane] = w;
    }
    __syncthreads();
    int excl = x - v + (wid > 0 ? wsum[wid - 1] : 0) + g_boff[blockIdx.x];
    if (i < n) { g_rowptr[i] = excl; g_cursor[i] = excl; }
}

__global__ void fill_kernel(const int* __restrict__ ei, int E) {
    const int4* src4 = (const int4*)ei;
    const int4* dst4 = (const int4*)(ei + E);
    const int E4 = E >> 2;
    for (int e = blockIdx.x * blockDim.x + threadIdx.x; e < E4; e += gridDim.x * blockDim.x) {
        int4 s = src4[e];
        int4 d = dst4[e];
        g_col[atomicAdd(&g_cursor[d.x], 1)] = s.x;
        g_col[atomicAdd(&g_cursor[d.y], 1)] = s.y;
        g_col[atomicAdd(&g_cursor[d.z], 1)] = s.z;
        g_col[atomicAdd(&g_cursor[d.w], 1)] = s.w;
    }
    int tail = E & 3;
    if (blockIdx.x == 0 && threadIdx.x < tail) {
        int e = (E & ~3) + threadIdx.x;
        g_col[atomicAdd(&g_cursor[ei[E + e]], 1)] = ei[e];
    }
}

// ---------------------------------------------------------------------------
__device__ __forceinline__ void mma_16x8x16(float& c0, float& c1, float& c2, float& c3,
                                            uint32_t a0, uint32_t a1, uint32_t a2, uint32_t a3,
                                            uint32_t b0, uint32_t b1) {
    asm volatile(
        "mma.sync.aligned.m16n8k16.row.col.f32.f16.f16.f32 "
        "{%0,%1,%2,%3}, {%4,%5,%6,%7}, {%8,%9}, {%0,%1,%2,%3};"
        : "+f"(c0), "+f"(c1), "+f"(c2), "+f"(c3)
        : "r"(a0), "r"(a1), "r"(a2), "r"(a3), "r"(b0), "r"(b1));
}

__global__ __launch_bounds__(256, 5) void layer_kernel(
    int in_sel, int out_sel, int layer_idx,
    const float* __restrict__ W1, const float* __restrict__ b1,
    const float* __restrict__ W2, const float* __restrict__ b2,
    const float* __restrict__ gamma, const float* __restrict__ beta,
    int n_nodes)
{
    const __half* __restrict__ hin  = (in_sel == 1) ? g_hA : g_hB;
    __half* __restrict__       hout = (out_sel == 1) ? g_hA : g_hB;

    __shared__ __align__(16) __half W1h[64 * RS];  // [n][k] transposed, fp16
    __shared__ __align__(16) __half W2h[64 * RS];
    __shared__ __align__(16) __half AT[64 * RS];   // agg tile [m][k]
    __shared__ __align__(16) __half UT[64 * RS];   // hidden tile [m][k]
    __shared__ float b1s[64], b2s[64], gs[64], bs[64];
    __shared__ int s_tile;

    const int tid = threadIdx.x;
    for (int i = tid; i < 4096; i += 256) {
        int k = i >> 6, n = i & 63;
        W1h[n * RS + k] = __float2half(W1[i]);
        W2h[n * RS + k] = __float2half(W2[i]);
    }
    if (tid < 64) { b1s[tid] = b1[tid]; b2s[tid] = b2[tid]; gs[tid] = gamma[tid]; bs[tid] = beta[tid]; }

    const int warp = tid >> 5, lane = tid & 31;
    const int gid = lane >> 2, tg = lane & 3;   // mma fragment coords
    const int m0 = (warp & 3) * 16;             // warp's output row block
    const int nb = (warp >> 2) * 32;            // warp's output col block
    const int c0 = 2 * lane;                    // gather channel pair

    const int ntiles = (n_nodes + TILE - 1) / TILE;
    for (;;) {
        if (tid == 0) s_tile = atomicAdd(&g_tilectr[layer_idx], 1);
        __syncthreads();
        const int tile = s_tile;
        if (tile >= ntiles) break;
        const int base = tile * TILE;

        // ---- phase 1: gather (warp-per-node, 8 nodes/warp) -> AT[m][k] ----
        #pragma unroll 1
        for (int i = 0; i < 8; i++) {
            const int m = warp * 8 + i;
            const int node = base + m;
            if (node < n_nodes) {
                float2 acc = __half22float2(*(const __half2*)(hin + (size_t)node * 64 + c0)); // self
                int j = g_rowptr[node];
                const int jend = g_rowptr[node + 1];
                #pragma unroll 1
                for (; j + 8 <= jend; j += 8) {
                    int s[8];
                    #pragma unroll
                    for (int q = 0; q < 8; q++) s[q] = g_col[j + q];
                    __half2 v[8];
                    #pragma unroll
                    for (int q = 0; q < 8; q++)
                        v[q] = *(const __half2*)(hin + (size_t)s[q] * 64 + c0);
                    float2 f0 = __half22float2(v[0]), f1 = __half22float2(v[1]);
                    float2 f2 = __half22float2(v[2]), f3 = __half22float2(v[3]);
                    float2 f4 = __half22float2(v[4]), f5 = __half22float2(v[5]);
                    float2 f6 = __half22float2(v[6]), f7 = __half22float2(v[7]);
                    acc.x += ((f0.x + f1.x) + (f2.x + f3.x)) + ((f4.x + f5.x) + (f6.x + f7.x));
                    acc.y += ((f0.y + f1.y) + (f2.y + f3.y)) + ((f4.y + f5.y) + (f6.y + f7.y));
                }
                for (; j < jend; j++) {
                    float2 v = __half22float2(*(const __half2*)(hin + (size_t)g_col[j] * 64 + c0));
                    acc.x += v.x; acc.y += v.y;
                }
                *(__half2*)(AT + m * RS + c0) = __floats2half2_rn(acc.x, acc.y);
            }
        }
        __syncthreads();   // AT complete

        // ---- phase 2a: U = relu(AT @ W1 + b1) via HMMA ----
        {
            float acc[4][4];
            #pragma unroll
            for (int nf = 0; nf < 4; nf++)
                #pragma unroll
                for (int q = 0; q < 4; q++) acc[nf][q] = 0.f;
            #pragma unroll
            for (int ks = 0; ks < 4; ks++) {
                const int k0 = ks * 16;
                uint32_t a0 = *(const uint32_t*)(AT + (m0 + gid)     * RS + k0 + 2 * tg);
                uint32_t a1 = *(const uint32_t*)(AT + (m0 + gid + 8) * RS + k0 + 2 * tg);
                uint32_t a2 = *(const uint32_t*)(AT + (m0 + gid)     * RS + k0 + 8 + 2 * tg);
                uint32_t a3 = *(const uint32_t*)(AT + (m0 + gid + 8) * RS + k0 + 8 + 2 * tg);
                #pragma unroll
                for (int nf = 0; nf < 4; nf++) {
                    const int n = nb + nf * 8 + gid;
                    uint32_t bb0 = *(const uint32_t*)(W1h + n * RS + k0 + 2 * tg);
                    uint32_t bb1 = *(const uint32_t*)(W1h + n * RS + k0 + 8 + 2 * tg);
                    mma_16x8x16(acc[nf][0], acc[nf][1], acc[nf][2], acc[nf][3],
                                a0, a1, a2, a3, bb0, bb1);
                }
            }
            #pragma unroll
            for (int nf = 0; nf < 4; nf++) {
                const int ncol = nb + nf * 8 + 2 * tg;
                float u0 = fmaxf(acc[nf][0] + b1s[ncol], 0.f);
                float u1 = fmaxf(acc[nf][1] + b1s[ncol + 1], 0.f);
                float u2 = fmaxf(acc[nf][2] + b1s[ncol], 0.f);
                float u3 = fmaxf(acc[nf][3] + b1s[ncol + 1], 0.f);
                *(__half2*)(UT + (m0 + gid)     * RS + ncol) = __floats2half2_rn(u0, u1);
                *(__half2*)(UT + (m0 + gid + 8) * RS + ncol) = __floats2half2_rn(u2, u3);
            }
        }
        __syncthreads();   // UT complete; all AT reads done

        // ---- phase 2b: V = relu(gamma*(UT @ W2 + b2) + beta) -> hout ----
        {
            float acc[4][4];
            #pragma unroll
            for (int nf = 0; nf < 4; nf++)
                #pragma unroll
                for (int q = 0; q < 4; q++) acc[nf][q] = 0.f;
            #pragma unroll
            for (int ks = 0; ks < 4; ks++) {
                const int k0 = ks * 16;
                uint32_t a0 = *(const uint32_t*)(UT + (m0 + gid)     * RS + k0 + 2 * tg);
                uint32_t a1 = *(const uint32_t*)(UT + (m0 + gid + 8) * RS + k0 + 2 * tg);
                uint32_t a2 = *(const uint32_t*)(UT + (m0 + gid)     * RS + k0 + 8 + 2 * tg);
                uint32_t a3 = *(const uint32_t*)(UT + (m0 + gid + 8) * RS + k0 + 8 + 2 * tg);
                #pragma unroll
                for (int nf = 0; nf < 4; nf++) {
                    const int n = nb + nf * 8 + gid;
                    uint32_t bb0 = *(const uint32_t*)(W2h + n * RS + k0 + 2 * tg);
                    uint32_t bb1 = *(const uint32_t*)(W2h + n * RS + k0 + 8 + 2 * tg);
                    mma_16x8x16(acc[nf][0], acc[nf][1], acc[nf][2], acc[nf][3],
                                a0, a1, a2, a3, bb0, bb1);
                }
            }
            const int row0 = base + m0 + gid;
            const int row1 = row0 + 8;
            #pragma unroll
            for (int nf = 0; nf < 4; nf++) {
                const int ncol = nb + nf * 8 + 2 * tg;
                float v0 = fmaxf(fmaf(acc[nf][0] + b2s[ncol],     gs[ncol],     bs[ncol]),     0.f);
                float v1 = fmaxf(fmaf(acc[nf][1] + b2s[ncol + 1], gs[ncol + 1], bs[ncol + 1]), 0.f);
                float v2 = fmaxf(fmaf(acc[nf][2] + b2s[ncol],     gs[ncol],     bs[ncol]),     0.f);
                float v3 = fmaxf(fmaf(acc[nf][3] + b2s[ncol + 1], gs[ncol + 1], bs[ncol + 1]), 0.f);
                if (row0 < n_nodes)
                    *(__half2*)(hout + (size_t)row0 * 64 + ncol) = __floats2half2_rn(v0, v1);
                if (row1 < n_nodes)
                    *(__half2*)(hout + (size_t)row1 * 64 + ncol) = __floats2half2_rn(v2, v3);
            }
        }
        __syncthreads();   // all UT reads done before next tile's s_tile write
    }
}

// ---------------------------------------------------------------------------
__device__ __forceinline__ int lower_bound_i(const int* a, int n, int key) {
    int lo = 0, hi = n;
    while (lo < hi) {
        int mid = (lo + hi) >> 1;
        if (a[mid] < key) lo = mid + 1; else hi = mid;
    }
    return lo;
}

// fused mean-pool + head: block g pools graph g's rows, then computes
// out[g] = relu(pooled @ fc1 + b1) @ fc2 + b2   (fc1: 64x32, fc2: 32x1)
__global__ void poolhead_kernel(const int* __restrict__ batch, int n_nodes,
                                const float* __restrict__ fc1W, const float* __restrict__ fc1b,
                                const float* __restrict__ fc2W, const float* __restrict__ fc2b,
                                float* __restrict__ out) {
    const __half* __restrict__ h = g_hB;  // final layer output lives in g_hB
    const int g = blockIdx.x;             // GMAX blocks, 256 threads
    const int lo = lower_bound_i(batch, n_nodes, g);
    const int hi = lower_bound_i(batch, n_nodes, g + 1);
    const int c = threadIdx.x & 63;
    const int r = threadIdx.x >> 6;
    float acc = 0.f;
    for (int i = lo + r; i < hi; i += 4) acc += __half2float(h[(size_t)i * 64 + c]);
    __shared__ float sh[256];
    __shared__ float pooled[64];
    sh[threadIdx.x] = acc;
    __syncthreads();
    if (threadIdx.x < 128) sh[threadIdx.x] += sh[threadIdx.x + 128];
    __syncthreads();
    if (threadIdx.x < 64) {
        float s = sh[threadIdx.x] + sh[threadIdx.x + 64];
        float cnt = (float)(hi - lo);
        pooled[threadIdx.x] = s / fmaxf(cnt, 1.f);
    }
    __syncthreads();
    if (threadIdx.x < 32) {                  // warp 0: hidden unit j = lane
        const int j = threadIdx.x;
        float a = fc1b[j];
        #pragma unroll
        for (int k = 0; k < 64; k++) a = fmaf(pooled[k], fc1W[k * 32 + j], a);
        float t = fmaxf(a, 0.f) * fc2W[j];
        #pragma unroll
        for (int o = 16; o > 0; o >>= 1) t += __shfl_down_sync(0xffffffffu, t, o);
        if (j == 0) out[g] = t + fc2b[0];
    }
}

// ---------------------------------------------------------------------------
extern "C" void kernel_launch(void* const* d_in, const int* in_sizes, int n_in,
                              void* d_out, int out_size) {
    const float* x     = (const float*)d_in[0];
    const int*   ei    = (const int*)d_in[1];
    const int*   batch = (const int*)d_in[2];
    const float* W1    = (const float*)d_in[3];
    const float* b1    = (const float*)d_in[4];
    const float* W2    = (const float*)d_in[5];
    const float* b2    = (const float*)d_in[6];
    const float* gamma = (const float*)d_in[7];
    const float* beta  = (const float*)d_in[8];
    const float* fc1W  = (const float*)d_in[9];
    const float* fc1b  = (const float*)d_in[10];
    const float* fc2W  = (const float*)d_in[11];
    const float* fc2b  = (const float*)d_in[12];
    float*       out   = (float*)d_out;

    const int N = in_sizes[0] / 64;
    const int E = in_sizes[1] / 2;
    const int G = out_size;
    const int NB = (N + SCB - 1) / SCB;

    // --- CSR build (dst -> src) + x -> half conversion ---
    init_kernel<<<(N * 64 / 4 + 255) / 256, 256>>>(x, N, N * 64);
    hist_kernel<<<1024, 256>>>(ei, E);
    bsum_kernel<<<NB, SCB>>>(N);
    bscan_kernel<<<1, 1024>>>(NB, N);
    scatter_scan_kernel<<<NB, SCB>>>(N);
    fill_kernel<<<1024, 256>>>(ei, E);

    // --- 3 fused GIN layers, ping-pong: A -> B -> A -> B ---
    const int LBLOCKS = 740;   // 5 blocks/SM target; tiles via work queue
    layer_kernel<<<LBLOCKS, 256>>>(1, 2, 0,
                                   W1 + 0 * 4096, b1 + 0 * 64, W2 + 0 * 4096, b2 + 0 * 64,
                                   gamma + 0 * 64, beta + 0 * 64, N);
    layer_kernel<<<LBLOCKS, 256>>>(2, 1, 1,
                                   W1 + 1 * 4096, b1 + 1 * 64, W2 + 1 * 4096, b2 + 1 * 64,
                                   gamma + 1 * 64, beta + 1 * 64, N);
    layer_kernel<<<LBLOCKS, 256>>>(1, 2, 2,
                                   W1 + 2 * 4096, b1 + 2 * 64, W2 + 2 * 4096, b2 + 2 * 64,
                                   gamma + 2 * 64, beta + 2 * 64, N);

    // --- fused mean pool + head ---
    poolhead_kernel<<<G, 256>>>(batch, N, fc1W, fc1b, fc2W, fc2b, out);
}

// round 11
// speedup vs baseline: 2.1175x; 1.0609x over previous
#include <cuda_runtime.h>
#include <cuda_fp16.h>
#include <cstdint>

// ---------------------------------------------------------------------------
// GIN regression: 3x (scatter-add agg + MLP(64->64->64) + BN-affine + ReLU),
// then per-graph mean pool + 2-layer head -> [128].
//
// FP16 node features. Gather: 4-edges-per-LDG.128 lane mapping (4 edge slots
// x 8 channel lanes), fp32 accumulation, shfl butterfly reduce. MLP on tensor
// cores (m16n8k16 f16f16f32). Dynamic work-queue tiles, 5 blocks/SM, fused
// pool+head.
// ---------------------------------------------------------------------------

#define NMAX 100000
#define EMAX 1600000
#define GMAX 128
#define TILE 64          // nodes per block tile
#define SCB  1024        // scan chunk
#define RS   72          // shared tile row stride in halves (pad 64 -> 72)

// scratch (device globals: allocation-free)
__device__ __align__(128) __half g_hA[(size_t)NMAX * 64];
__device__ __align__(128) __half g_hB[(size_t)NMAX * 64];
__device__ int    g_deg[NMAX];
__device__ int    g_rowptr[NMAX + 1];
__device__ int    g_cursor[NMAX];
__device__ int    g_col[EMAX];
__device__ int    g_bsum[128];
__device__ int    g_boff[128];
__device__ int    g_tilectr[3];

// ---------------------------------------------------------------------------
// fused: zero deg/tilectr + convert x to fp16
__global__ void init_kernel(const float* __restrict__ x, int n_nodes, int n64) {
    int t = blockIdx.x * blockDim.x + threadIdx.x;
    if (t < n_nodes) g_deg[t] = 0;
    if (t < 3) g_tilectr[t] = 0;
    int i = t * 4;
    if (i < n64) {
        float4 f = *(const float4*)(x + i);
        *(__half2*)(g_hA + i)     = __floats2half2_rn(f.x, f.y);
        *(__half2*)(g_hA + i + 2) = __floats2half2_rn(f.z, f.w);
    }
}

__global__ void hist_kernel(const int* __restrict__ ei, int E) {
    const int4* dst4 = (const int4*)(ei + E);
    const int E4 = E >> 2;
    for (int e = blockIdx.x * blockDim.x + threadIdx.x; e < E4; e += gridDim.x * blockDim.x) {
        int4 d = dst4[e];
        atomicAdd(&g_deg[d.x], 1);
        atomicAdd(&g_deg[d.y], 1);
        atomicAdd(&g_deg[d.z], 1);
        atomicAdd(&g_deg[d.w], 1);
    }
    int tail = E & 3;
    if (blockIdx.x == 0 && threadIdx.x < tail)
        atomicAdd(&g_deg[ei[E + (E & ~3) + threadIdx.x]], 1);
}

__global__ void bsum_kernel(int n) {
    __shared__ int sh[32];
    int i = blockIdx.x * SCB + threadIdx.x;
    int v = (i < n) ? g_deg[i] : 0;
    #pragma unroll
    for (int o = 16; o > 0; o >>= 1) v += __shfl_down_sync(0xffffffffu, v, o);
    if ((threadIdx.x & 31) == 0) sh[threadIdx.x >> 5] = v;
    __syncthreads();
    if (threadIdx.x < 32) {
        int w = sh[threadIdx.x];
        #pragma unroll
        for (int o = 16; o > 0; o >>= 1) w += __shfl_down_sync(0xffffffffu, w, o);
        if (threadIdx.x == 0) g_bsum[blockIdx.x] = w;
    }
}

__global__ void bscan_kernel(int nb, int n) {   // 1 block, 1024 threads
    __shared__ int wsum[32];
    const int tid = threadIdx.x, lane = tid & 31, wid = tid >> 5;
    int v = (tid < nb) ? g_bsum[tid] : 0;
    int x = v;
    #pragma unroll
    for (int o = 1; o < 32; o <<= 1) {
        int y = __shfl_up_sync(0xffffffffu, x, o);
        if (lane >= o) x += y;
    }
    if (lane == 31) wsum[wid] = x;
    __syncthreads();
    if (wid == 0) {
        int w = wsum[lane];
        #pragma unroll
        for (int o = 1; o < 32; o <<= 1) {
            int y = __shfl_up_sync(0xffffffffu, w, o);
            if (lane >= o) w += y;
        }
        wsum[lane] = w;
    }
    __syncthreads();
    int excl = x - v + (wid > 0 ? wsum[wid - 1] : 0);
    if (tid < nb) g_boff[tid] = excl;
    if (tid == nb - 1) g_rowptr[n] = excl + v;   // == E
}

__global__ void scatter_scan_kernel(int n) {
    __shared__ int wsum[32];
    const int tid = threadIdx.x, lane = tid & 31, wid = tid >> 5;
    int i = blockIdx.x * SCB + tid;
    int v = (i < n) ? g_deg[i] : 0;
    int x = v;
    #pragma unroll
    for (int o = 1; o < 32; o <<= 1) {
        int y = __shfl_up_sync(0xffffffffu, x, o);
        if (lane >= o) x += y;
    }
    if (lane == 31) wsum[wid] = x;
    __syncthreads();
    if (wid == 0) {
        int w = wsum[lane];
        #pragma unroll
        for (int o = 1; o < 32; o <<= 1) {
            int y = __shfl_up_sync(0xffffffffu, w, o);
            if (lane >= o) w += y;
        }
        wsum[lane] = w;
    }
    __syncthreads();
    int excl = x - v + (wid > 0 ? wsum[wid - 1] : 0) + g_boff[blockIdx.x];
    if (i < n) { g_rowptr[i] = excl; g_cursor[i] = excl; }
}

__global__ void fill_kernel(const int* __restrict__ ei, int E) {
    const int4* src4 = (const int4*)ei;
    const int4* dst4 = (const int4*)(ei + E);
    const int E4 = E >> 2;
    for (int e = blockIdx.x * blockDim.x + threadIdx.x; e < E4; e += gridDim.x * blockDim.x) {
        int4 s = src4[e];
        int4 d = dst4[e];
        g_col[atomicAdd(&g_cursor[d.x], 1)] = s.x;
        g_col[atomicAdd(&g_cursor[d.y], 1)] = s.y;
        g_col[atomicAdd(&g_cursor[d.z], 1)] = s.z;
        g_col[atomicAdd(&g_cursor[d.w], 1)] = s.w;
    }
    int tail = E & 3;
    if (blockIdx.x == 0 && threadIdx.x < tail) {
        int e = (E & ~3) + threadIdx.x;
        g_col[atomicAdd(&g_cursor[ei[E + e]], 1)] = ei[e];
    }
}

// ---------------------------------------------------------------------------
__device__ __forceinline__ void mma_16x8x16(float& c0, float& c1, float& c2, float& c3,
                                            uint32_t a0, uint32_t a1, uint32_t a2, uint32_t a3,
                                            uint32_t b0, uint32_t b1) {
    asm volatile(
        "mma.sync.aligned.m16n8k16.row.col.f32.f16.f16.f32 "
        "{%0,%1,%2,%3}, {%4,%5,%6,%7}, {%8,%9}, {%0,%1,%2,%3};"
        : "+f"(c0), "+f"(c1), "+f"(c2), "+f"(c3)
        : "r"(a0), "r"(a1), "r"(a2), "r"(a3), "r"(b0), "r"(b1));
}

__device__ __forceinline__ void acc_add8(float* a, uint4 r) {
    float2 f;
    f = __half22float2(*(__half2*)&r.x); a[0] += f.x; a[1] += f.y;
    f = __half22float2(*(__half2*)&r.y); a[2] += f.x; a[3] += f.y;
    f = __half22float2(*(__half2*)&r.z); a[4] += f.x; a[5] += f.y;
    f = __half22float2(*(__half2*)&r.w); a[6] += f.x; a[7] += f.y;
}

__global__ __launch_bounds__(256, 5) void layer_kernel(
    int in_sel, int out_sel, int layer_idx,
    const float* __restrict__ W1, const float* __restrict__ b1,
    const float* __restrict__ W2, const float* __restrict__ b2,
    const float* __restrict__ gamma, const float* __restrict__ beta,
    int n_nodes)
{
    const __half* __restrict__ hin  = (in_sel == 1) ? g_hA : g_hB;
    __half* __restrict__       hout = (out_sel == 1) ? g_hA : g_hB;

    __shared__ __align__(16) __half W1h[64 * RS];  // [n][k] transposed, fp16
    __shared__ __align__(16) __half W2h[64 * RS];
    __shared__ __align__(16) __half AT[64 * RS];   // agg tile [m][k]
    __shared__ __align__(16) __half UT[64 * RS];   // hidden tile [m][k]
    __shared__ float b1s[64], b2s[64], gs[64], bs[64];
    __shared__ int s_tile;

    const int tid = threadIdx.x;
    for (int i = tid; i < 4096; i += 256) {
        int k = i >> 6, n = i & 63;
        W1h[n * RS + k] = __float2half(W1[i]);
        W2h[n * RS + k] = __float2half(W2[i]);
    }
    if (tid < 64) { b1s[tid] = b1[tid]; b2s[tid] = b2[tid]; gs[tid] = gamma[tid]; bs[tid] = beta[tid]; }

    const int warp = tid >> 5, lane = tid & 31;
    const int gid = lane >> 2, tg = lane & 3;   // mma fragment coords
    const int m0 = (warp & 3) * 16;             // warp's output row block
    const int nb = (warp >> 2) * 32;            // warp's output col block
    const int qg = lane >> 3;                   // gather: edge slot (0..3)
    const int cbase = (lane & 7) * 8;           // gather: channel octet base

    const int ntiles = (n_nodes + TILE - 1) / TILE;
    for (;;) {
        if (tid == 0) s_tile = atomicAdd(&g_tilectr[layer_idx], 1);
        __syncthreads();
        const int tile = s_tile;
        if (tile >= ntiles) break;
        const int base = tile * TILE;

        // ---- phase 1: gather (warp-per-node; 4 edge slots x 8 chan lanes) ----
        #pragma unroll 1
        for (int i = 0; i < 8; i++) {
            const int m = warp * 8 + i;
            const int node = base + m;            // uniform across warp
            if (node < n_nodes) {
                float acc[8];
                if (qg == 0) {                    // self term (eps=0), slot 0 only
                    uint4 r = *(const uint4*)(hin + (size_t)node * 64 + cbase);
                    float2 f;
                    f = __half22float2(*(__half2*)&r.x); acc[0] = f.x; acc[1] = f.y;
                    f = __half22float2(*(__half2*)&r.y); acc[2] = f.x; acc[3] = f.y;
                    f = __half22float2(*(__half2*)&r.z); acc[4] = f.x; acc[5] = f.y;
                    f = __half22float2(*(__half2*)&r.w); acc[6] = f.x; acc[7] = f.y;
                } else {
                    #pragma unroll
                    for (int t = 0; t < 8; t++) acc[t] = 0.f;
                }
                int j = g_rowptr[node];
                const int jend = g_rowptr[node + 1];
                #pragma unroll 1
                for (; j + 8 <= jend; j += 8) {
                    int sA = g_col[j + qg];           // 4 lanes-groups, 1 line
                    int sB = g_col[j + 4 + qg];
                    uint4 ra = *(const uint4*)(hin + (size_t)sA * 64 + cbase);
                    uint4 rb = *(const uint4*)(hin + (size_t)sB * 64 + cbase);
                    acc_add8(acc, ra);
                    acc_add8(acc, rb);
                }
                const int rem = jend - j;
                if (qg < rem) {
                    int sA = g_col[j + qg];
                    uint4 ra = *(const uint4*)(hin + (size_t)sA * 64 + cbase);
                    acc_add8(acc, ra);
                }
                if (qg + 4 < rem) {
                    int sB = g_col[j + 4 + qg];
                    uint4 rb = *(const uint4*)(hin + (size_t)sB * 64 + cbase);
                    acc_add8(acc, rb);
                }
                // butterfly across edge slots (lane bits 3,4)
                #pragma unroll
                for (int t = 0; t < 8; t++) {
                    acc[t] += __shfl_xor_sync(0xffffffffu, acc[t], 8);
                    acc[t] += __shfl_xor_sync(0xffffffffu, acc[t], 16);
                }
                if (lane < 8) {                   // lanes 0-7 store full row
                    __half2 h0 = __floats2half2_rn(acc[0], acc[1]);
                    __half2 h1 = __floats2half2_rn(acc[2], acc[3]);
                    __half2 h2 = __floats2half2_rn(acc[4], acc[5]);
                    __half2 h3 = __floats2half2_rn(acc[6], acc[7]);
                    uint4 st;
                    st.x = *(uint32_t*)&h0; st.y = *(uint32_t*)&h1;
                    st.z = *(uint32_t*)&h2; st.w = *(uint32_t*)&h3;
                    *(uint4*)(AT + m * RS + cbase) = st;   // 144B row stride: 16B aligned
                }
            }
        }
        __syncthreads();   // AT complete

        // ---- phase 2a: U = relu(AT @ W1 + b1) via HMMA ----
        {
            float acc[4][4];
            #pragma unroll
            for (int nf = 0; nf < 4; nf++)
                #pragma unroll
                for (int q = 0; q < 4; q++) acc[nf][q] = 0.f;
            #pragma unroll
            for (int ks = 0; ks < 4; ks++) {
                const int k0 = ks * 16;
                uint32_t a0 = *(const uint32_t*)(AT + (m0 + gid)     * RS + k0 + 2 * tg);
                uint32_t a1 = *(const uint32_t*)(AT + (m0 + gid + 8) * RS + k0 + 2 * tg);
                uint32_t a2 = *(const uint32_t*)(AT + (m0 + gid)     * RS + k0 + 8 + 2 * tg);
                uint32_t a3 = *(const uint32_t*)(AT + (m0 + gid + 8) * RS + k0 + 8 + 2 * tg);
                #pragma unroll
                for (int nf = 0; nf < 4; nf++) {
                    const int n = nb + nf * 8 + gid;
                    uint32_t bb0 = *(const uint32_t*)(W1h + n * RS + k0 + 2 * tg);
                    uint32_t bb1 = *(const uint32_t*)(W1h + n * RS + k0 + 8 + 2 * tg);
                    mma_16x8x16(acc[nf][0], acc[nf][1], acc[nf][2], acc[nf][3],
                                a0, a1, a2, a3, bb0, bb1);
                }
            }
            #pragma unroll
            for (int nf = 0; nf < 4; nf++) {
                const int ncol = nb + nf * 8 + 2 * tg;
                float u0 = fmaxf(acc[nf][0] + b1s[ncol], 0.f);
                float u1 = fmaxf(acc[nf][1] + b1s[ncol + 1], 0.f);
                float u2 = fmaxf(acc[nf][2] + b1s[ncol], 0.f);
                float u3 = fmaxf(acc[nf][3] + b1s[ncol + 1], 0.f);
                *(__half2*)(UT + (m0 + gid)     * RS + ncol) = __floats2half2_rn(u0, u1);
                *(__half2*)(UT + (m0 + gid + 8) * RS + ncol) = __floats2half2_rn(u2, u3);
            }
        }
        __syncthreads();   // UT complete; all AT reads done

        // ---- phase 2b: V = relu(gamma*(UT @ W2 + b2) + beta) -> hout ----
        {
            float acc[4][4];
            #pragma unroll
            for (int nf = 0; nf < 4; nf++)
                #pragma unroll
                for (int q = 0; q < 4; q++) acc[nf][q] = 0.f;
            #pragma unroll
            for (int ks = 0; ks < 4; ks++) {
                const int k0 = ks * 16;
                uint32_t a0 = *(const uint32_t*)(UT + (m0 + gid)     * RS + k0 + 2 * tg);
                uint32_t a1 = *(const uint32_t*)(UT + (m0 + gid + 8) * RS + k0 + 2 * tg);
                uint32_t a2 = *(const uint32_t*)(UT + (m0 + gid)     * RS + k0 + 8 + 2 * tg);
                uint32_t a3 = *(const uint32_t*)(UT + (m0 + gid + 8) * RS + k0 + 8 + 2 * tg);
                #pragma unroll
                for (int nf = 0; nf < 4; nf++) {
                    const int n = nb + nf * 8 + gid;
                    uint32_t bb0 = *(const uint32_t*)(W2h + n * RS + k0 + 2 * tg);
                    uint32_t bb1 = *(const uint32_t*)(W2h + n * RS + k0 + 8 + 2 * tg);
                    mma_16x8x16(acc[nf][0], acc[nf][1], acc[nf][2], acc[nf][3],
                                a0, a1, a2, a3, bb0, bb1);
                }
            }
            const int row0 = base + m0 + gid;
            const int row1 = row0 + 8;
            #pragma unroll
            for (int nf = 0; nf < 4; nf++) {
                const int ncol = nb + nf * 8 + 2 * tg;
                float v0 = fmaxf(fmaf(acc[nf][0] + b2s[ncol],     gs[ncol],     bs[ncol]),     0.f);
                float v1 = fmaxf(fmaf(acc[nf][1] + b2s[ncol + 1], gs[ncol + 1], bs[ncol + 1]), 0.f);
                float v2 = fmaxf(fmaf(acc[nf][2] + b2s[ncol],     gs[ncol],     bs[ncol]),     0.f);
                float v3 = fmaxf(fmaf(acc[nf][3] + b2s[ncol + 1], gs[ncol + 1], bs[ncol + 1]), 0.f);
                if (row0 < n_nodes)
                    *(__half2*)(hout + (size_t)row0 * 64 + ncol) = __floats2half2_rn(v0, v1);
                if (row1 < n_nodes)
                    *(__half2*)(hout + (size_t)row1 * 64 + ncol) = __floats2half2_rn(v2, v3);
            }
        }
        __syncthreads();   // all UT reads done before next tile's s_tile write
    }
}

// ---------------------------------------------------------------------------
__device__ __forceinline__ int lower_bound_i(const int* a, int n, int key) {
    int lo = 0, hi = n;
    while (lo < hi) {
        int mid = (lo + hi) >> 1;
        if (a[mid] < key) lo = mid + 1; else hi = mid;
    }
    return lo;
}

// fused mean-pool + head
__global__ void poolhead_kernel(const int* __restrict__ batch, int n_nodes,
                                const float* __restrict__ fc1W, const float* __restrict__ fc1b,
                                const float* __restrict__ fc2W, const float* __restrict__ fc2b,
                                float* __restrict__ out) {
    const __half* __restrict__ h = g_hB;  // final layer output lives in g_hB
    const int g = blockIdx.x;
    const int lo = lower_bound_i(batch, n_nodes, g);
    const int hi = lower_bound_i(batch, n_nodes, g + 1);
    const int c = threadIdx.x & 63;
    const int r = threadIdx.x >> 6;
    float acc = 0.f;
    for (int i = lo + r; i < hi; i += 4) acc += __half2float(h[(size_t)i * 64 + c]);
    __shared__ float sh[256];
    __shared__ float pooled[64];
    sh[threadIdx.x] = acc;
    __syncthreads();
    if (threadIdx.x < 128) sh[threadIdx.x] += sh[threadIdx.x + 128];
    __syncthreads();
    if (threadIdx.x < 64) {
        float s = sh[threadIdx.x] + sh[threadIdx.x + 64];
        float cnt = (float)(hi - lo);
        pooled[threadIdx.x] = s / fmaxf(cnt, 1.f);
    }
    __syncthreads();
    if (threadIdx.x < 32) {
        const int j = threadIdx.x;
        float a = fc1b[j];
        #pragma unroll
        for (int k = 0; k < 64; k++) a = fmaf(pooled[k], fc1W[k * 32 + j], a);
        float t = fmaxf(a, 0.f) * fc2W[j];
        #pragma unroll
        for (int o = 16; o > 0; o >>= 1) t += __shfl_down_sync(0xffffffffu, t, o);
        if (j == 0) out[g] = t + fc2b[0];
    }
}

// ---------------------------------------------------------------------------
extern "C" void kernel_launch(void* const* d_in, const int* in_sizes, int n_in,
                              void* d_out, int out_size) {
    const float* x     = (const float*)d_in[0];
    const int*   ei    = (const int*)d_in[1];
    const int*   batch = (const int*)d_in[2];
    const float* W1    = (const float*)d_in[3];
    const float* b1    = (const float*)d_in[4];
    const float* W2    = (const float*)d_in[5];
    const float* b2    = (const float*)d_in[6];
    const float* gamma = (const float*)d_in[7];
    const float* beta  = (const float*)d_in[8];
    const float* fc1W  = (const float*)d_in[9];
    const float* fc1b  = (const float*)d_in[10];
    const float* fc2W  = (const float*)d_in[11];
    const float* fc2b  = (const float*)d_in[12];
    float*       out   = (float*)d_out;

    const int N = in_sizes[0] / 64;
    const int E = in_sizes[1] / 2;
    const int G = out_size;
    const int NB = (N + SCB - 1) / SCB;

    // --- CSR build (dst -> src) + x -> half conversion ---
    init_kernel<<<(N * 64 / 4 + 255) / 256, 256>>>(x, N, N * 64);
    hist_kernel<<<1024, 256>>>(ei, E);
    bsum_kernel<<<NB, SCB>>>(N);
    bscan_kernel<<<1, 1024>>>(NB, N);
    scatter_scan_kernel<<<NB, SCB>>>(N);
    fill_kernel<<<1024, 256>>>(ei, E);

    // --- 3 fused GIN layers, ping-pong: A -> B -> A -> B ---
    const int LBLOCKS = 740;   // 5 blocks/SM; tiles via work queue
    layer_kernel<<<LBLOCKS, 256>>>(1, 2, 0,
                                   W1 + 0 * 4096, b1 + 0 * 64, W2 + 0 * 4096, b2 + 0 * 64,
                                   gamma + 0 * 64, beta + 0 * 64, N);
    layer_kernel<<<LBLOCKS, 256>>>(2, 1, 1,
                                   W1 + 1 * 4096, b1 + 1 * 64, W2 + 1 * 4096, b2 + 1 * 64,
                                   gamma + 1 * 64, beta + 1 * 64, N);
    layer_kernel<<<LBLOCKS, 256>>>(1, 2, 2,
                                   W1 + 2 * 4096, b1 + 2 * 64, W2 + 2 * 4096, b2 + 2 * 64,
                                   gamma + 2 * 64, beta + 2 * 64, N);

    // --- fused mean pool + head ---
    poolhead_kernel<<<G, 256>>>(batch, N, fc1W, fc1b, fc2W, fc2b, out);
}

// round 12
// speedup vs baseline: 2.1178x; 1.0001x over previous
#include <cuda_runtime.h>
#include <cuda_fp16.h>
#include <cstdint>

// ---------------------------------------------------------------------------
// GIN regression: 3x (scatter-add agg + MLP(64->64->64) + BN-affine + ReLU),
// then per-graph mean pool + 2-layer head -> [128].
//
// FP16 node features. Gather: 4-edges-per-LDG.128 lane mapping with
// NODE-PAIR INTERLEAVING (two independent load chains in flight per warp),
// fp32 accumulation, shfl butterfly reduce. MLP on tensor cores
// (m16n8k16 f16f16f32). Dynamic work-queue tiles, 5 blocks/SM, fused
// pool+head.
// ---------------------------------------------------------------------------

#define NMAX 100000
#define EMAX 1600000
#define GMAX 128
#define TILE 64          // nodes per block tile
#define SCB  1024        // scan chunk
#define RS   72          // shared tile row stride in halves (pad 64 -> 72)

// scratch (device globals: allocation-free)
__device__ __align__(128) __half g_hA[(size_t)NMAX * 64];
__device__ __align__(128) __half g_hB[(size_t)NMAX * 64];
__device__ int    g_deg[NMAX];
__device__ int    g_rowptr[NMAX + 1];
__device__ int    g_cursor[NMAX];
__device__ int    g_col[EMAX];
__device__ int    g_bsum[128];
__device__ int    g_boff[128];
__device__ int    g_tilectr[3];

// ---------------------------------------------------------------------------
// fused: zero deg/tilectr + convert x to fp16
__global__ void init_kernel(const float* __restrict__ x, int n_nodes, int n64) {
    int t = blockIdx.x * blockDim.x + threadIdx.x;
    if (t < n_nodes) g_deg[t] = 0;
    if (t < 3) g_tilectr[t] = 0;
    int i = t * 4;
    if (i < n64) {
        float4 f = *(const float4*)(x + i);
        *(__half2*)(g_hA + i)     = __floats2half2_rn(f.x, f.y);
        *(__half2*)(g_hA + i + 2) = __floats2half2_rn(f.z, f.w);
    }
}

__global__ void hist_kernel(const int* __restrict__ ei, int E) {
    const int4* dst4 = (const int4*)(ei + E);
    const int E4 = E >> 2;
    for (int e = blockIdx.x * blockDim.x + threadIdx.x; e < E4; e += gridDim.x * blockDim.x) {
        int4 d = dst4[e];
        atomicAdd(&g_deg[d.x], 1);
        atomicAdd(&g_deg[d.y], 1);
        atomicAdd(&g_deg[d.z], 1);
        atomicAdd(&g_deg[d.w], 1);
    }
    int tail = E & 3;
    if (blockIdx.x == 0 && threadIdx.x < tail)
        atomicAdd(&g_deg[ei[E + (E & ~3) + threadIdx.x]], 1);
}

__global__ void bsum_kernel(int n) {
    __shared__ int sh[32];
    int i = blockIdx.x * SCB + threadIdx.x;
    int v = (i < n) ? g_deg[i] : 0;
    #pragma unroll
    for (int o = 16; o > 0; o >>= 1) v += __shfl_down_sync(0xffffffffu, v, o);
    if ((threadIdx.x & 31) == 0) sh[threadIdx.x >> 5] = v;
    __syncthreads();
    if (threadIdx.x < 32) {
        int w = sh[threadIdx.x];
        #pragma unroll
        for (int o = 16; o > 0; o >>= 1) w += __shfl_down_sync(0xffffffffu, w, o);
        if (threadIdx.x == 0) g_bsum[blockIdx.x] = w;
    }
}

__global__ void bscan_kernel(int nb, int n) {   // 1 block, 1024 threads
    __shared__ int wsum[32];
    const int tid = threadIdx.x, lane = tid & 31, wid = tid >> 5;
    int v = (tid < nb) ? g_bsum[tid] : 0;
    int x = v;
    #pragma unroll
    for (int o = 1; o < 32; o <<= 1) {
        int y = __shfl_up_sync(0xffffffffu, x, o);
        if (lane >= o) x += y;
    }
    if (lane == 31) wsum[wid] = x;
    __syncthreads();
    if (wid == 0) {
        int w = wsum[lane];
        #pragma unroll
        for (int o = 1; o < 32; o <<= 1) {
            int y = __shfl_up_sync(0xffffffffu, w, o);
            if (lane >= o) w += y;
        }
        wsum[lane] = w;
    }
    __syncthreads();
    int excl = x - v + (wid > 0 ? wsum[wid - 1] : 0);
    if (tid < nb) g_boff[tid] = excl;
    if (tid == nb - 1) g_rowptr[n] = excl + v;   // == E
}

__global__ void scatter_scan_kernel(int n) {
    __shared__ int wsum[32];
    const int tid = threadIdx.x, lane = tid & 31, wid = tid >> 5;
    int i = blockIdx.x * SCB + tid;
    int v = (i < n) ? g_deg[i] : 0;
    int x = v;
    #pragma unroll
    for (int o = 1; o < 32; o <<= 1) {
        int y = __shfl_up_sync(0xffffffffu, x, o);
        if (lane >= o) x += y;
    }
    if (lane == 31) wsum[wid] = x;
    __syncthreads();
    if (wid == 0) {
        int w = wsum[lane];
        #pragma unroll
        for (int o = 1; o < 32; o <<= 1) {
            int y = __shfl_up_sync(0xffffffffu, w, o);
            if (lane >= o) w += y;
        }
        wsum[lane] = w;
    }
    __syncthreads();
    int excl = x - v + (wid > 0 ? wsum[wid - 1] : 0) + g_boff[blockIdx.x];
    if (i < n) { g_rowptr[i] = excl; g_cursor[i] = excl; }
}

__global__ void fill_kernel(const int* __restrict__ ei, int E) {
    const int4* src4 = (const int4*)ei;
    const int4* dst4 = (const int4*)(ei + E);
    const int E4 = E >> 2;
    for (int e = blockIdx.x * blockDim.x + threadIdx.x; e < E4; e += gridDim.x * blockDim.x) {
        int4 s = src4[e];
        int4 d = dst4[e];
        g_col[atomicAdd(&g_cursor[d.x], 1)] = s.x;
        g_col[atomicAdd(&g_cursor[d.y], 1)] = s.y;
        g_col[atomicAdd(&g_cursor[d.z], 1)] = s.z;
        g_col[atomicAdd(&g_cursor[d.w], 1)] = s.w;
    }
    int tail = E & 3;
    if (blockIdx.x == 0 && threadIdx.x < tail) {
        int e = (E & ~3) + threadIdx.x;
        g_col[atomicAdd(&g_cursor[ei[E + e]], 1)] = ei[e];
    }
}

// ---------------------------------------------------------------------------
__device__ __forceinline__ void mma_16x8x16(float& c0, float& c1, float& c2, float& c3,
                                            uint32_t a0, uint32_t a1, uint32_t a2, uint32_t a3,
                                            uint32_t b0, uint32_t b1) {
    asm volatile(
        "mma.sync.aligned.m16n8k16.row.col.f32.f16.f16.f32 "
        "{%0,%1,%2,%3}, {%4,%5,%6,%7}, {%8,%9}, {%0,%1,%2,%3};"
        : "+f"(c0), "+f"(c1), "+f"(c2), "+f"(c3)
        : "r"(a0), "r"(a1), "r"(a2), "r"(a3), "r"(b0), "r"(b1));
}

__device__ __forceinline__ void acc_add8(float* a, uint4 r) {
    float2 f;
    f = __half22float2(*(__half2*)&r.x); a[0] += f.x; a[1] += f.y;
    f = __half22float2(*(__half2*)&r.y); a[2] += f.x; a[3] += f.y;
    f = __half22float2(*(__half2*)&r.z); a[4] += f.x; a[5] += f.y;
    f = __half22float2(*(__half2*)&r.w); a[6] += f.x; a[7] += f.y;
}

// gather one node's remainder (<8 edges) and butterfly+store its row
__device__ __forceinline__ void gather_tail_store(
    const __half* __restrict__ hin, __half* __restrict__ AT,
    float* acc, int j, int jend, int qg, int cbase, int lane, int m)
{
    const int rem = jend - j;
    if (qg < rem) {
        int sA = g_col[j + qg];
        uint4 ra = *(const uint4*)(hin + (size_t)sA * 64 + cbase);
        acc_add8(acc, ra);
    }
    if (qg + 4 < rem) {
        int sB = g_col[j + 4 + qg];
        uint4 rb = *(const uint4*)(hin + (size_t)sB * 64 + cbase);
        acc_add8(acc, rb);
    }
    #pragma unroll
    for (int t = 0; t < 8; t++) {
        acc[t] += __shfl_xor_sync(0xffffffffu, acc[t], 8);
        acc[t] += __shfl_xor_sync(0xffffffffu, acc[t], 16);
    }
    if (lane < 8) {
        __half2 h0 = __floats2half2_rn(acc[0], acc[1]);
        __half2 h1 = __floats2half2_rn(acc[2], acc[3]);
        __half2 h2 = __floats2half2_rn(acc[4], acc[5]);
        __half2 h3 = __floats2half2_rn(acc[6], acc[7]);
        uint4 st;
        st.x = *(uint32_t*)&h0; st.y = *(uint32_t*)&h1;
        st.z = *(uint32_t*)&h2; st.w = *(uint32_t*)&h3;
        *(uint4*)(AT + m * RS + cbase) = st;
    }
}

__global__ __launch_bounds__(256, 5) void layer_kernel(
    int in_sel, int out_sel, int layer_idx,
    const float* __restrict__ W1, const float* __restrict__ b1,
    const float* __restrict__ W2, const float* __restrict__ b2,
    const float* __restrict__ gamma, const float* __restrict__ beta,
    int n_nodes)
{
    const __half* __restrict__ hin  = (in_sel == 1) ? g_hA : g_hB;
    __half* __restrict__       hout = (out_sel == 1) ? g_hA : g_hB;

    __shared__ __align__(16) __half W1h[64 * RS];  // [n][k] transposed, fp16
    __shared__ __align__(16) __half W2h[64 * RS];
    __shared__ __align__(16) __half AT[64 * RS];   // agg tile [m][k]
    __shared__ __align__(16) __half UT[64 * RS];   // hidden tile [m][k]
    __shared__ float b1s[64], b2s[64], gs[64], bs[64];
    __shared__ int s_tile;

    const int tid = threadIdx.x;
    for (int i = tid; i < 4096; i += 256) {
        int k = i >> 6, n = i & 63;
        W1h[n * RS + k] = __float2half(W1[i]);
        W2h[n * RS + k] = __float2half(W2[i]);
    }
    if (tid < 64) { b1s[tid] = b1[tid]; b2s[tid] = b2[tid]; gs[tid] = gamma[tid]; bs[tid] = beta[tid]; }

    const int warp = tid >> 5, lane = tid & 31;
    const int gid = lane >> 2, tg = lane & 3;   // mma fragment coords
    const int m0 = (warp & 3) * 16;             // warp's output row block
    const int nb = (warp >> 2) * 32;            // warp's output col block
    const int qg = lane >> 3;                   // gather: edge slot (0..3)
    const int cbase = (lane & 7) * 8;           // gather: channel octet base

    const int ntiles = (n_nodes + TILE - 1) / TILE;
    for (;;) {
        if (tid == 0) s_tile = atomicAdd(&g_tilectr[layer_idx], 1);
        __syncthreads();       // s_tile ready; also orders prior-tile UT reads
        const int tile = s_tile;
        if (tile >= ntiles) break;
        const int base = tile * TILE;

        // ---- phase 1: gather, node-PAIR interleaved (2 chains in flight) ----
        #pragma unroll 1
        for (int i = 0; i < 4; i++) {
            const int mA = warp * 8 + 2 * i;
            const int mB = mA + 1;
            const int nodeA = base + mA;            // uniform across warp
            const int nodeB = base + mB;
            const bool hasA = (nodeA < n_nodes);
            const bool hasB = (nodeB < n_nodes);
            float acc0[8], acc1[8];
            #pragma unroll
            for (int t = 0; t < 8; t++) { acc0[t] = 0.f; acc1[t] = 0.f; }
            if (qg == 0) {                          // self term (eps=0), slot 0
                if (hasA) {
                    uint4 r = *(const uint4*)(hin + (size_t)nodeA * 64 + cbase);
                    acc_add8(acc0, r);
                }
                if (hasB) {
                    uint4 r = *(const uint4*)(hin + (size_t)nodeB * 64 + cbase);
                    acc_add8(acc1, r);
                }
            }
            int j0 = 0, e0 = 0, j1 = 0, e1 = 0;
            if (hasA) { j0 = g_rowptr[nodeA]; e0 = g_rowptr[nodeA + 1]; }
            if (hasB) { j1 = g_rowptr[nodeB]; e1 = g_rowptr[nodeB + 1]; }
            #pragma unroll 1
            for (;;) {
                const bool p0 = (j0 + 8 <= e0);     // warp-uniform
                const bool p1 = (j1 + 8 <= e1);
                if (!p0 && !p1) break;
                int sA0, sB0, sA1, sB1;
                if (p0) { sA0 = g_col[j0 + qg]; sB0 = g_col[j0 + 4 + qg]; }
                if (p1) { sA1 = g_col[j1 + qg]; sB1 = g_col[j1 + 4 + qg]; }
                if (p0) {
                    uint4 ra = *(const uint4*)(hin + (size_t)sA0 * 64 + cbase);
                    uint4 rb = *(const uint4*)(hin + (size_t)sB0 * 64 + cbase);
                    acc_add8(acc0, ra);
                    acc_add8(acc0, rb);
                    j0 += 8;
                }
                if (p1) {
                    uint4 ra = *(const uint4*)(hin + (size_t)sA1 * 64 + cbase);
                    uint4 rb = *(const uint4*)(hin + (size_t)sB1 * 64 + cbase);
                    acc_add8(acc1, ra);
                    acc_add8(acc1, rb);
                    j1 += 8;
                }
            }
            if (hasA) gather_tail_store(hin, AT, acc0, j0, e0, qg, cbase, lane, mA);
            if (hasB) gather_tail_store(hin, AT, acc1, j1, e1, qg, cbase, lane, mB);
        }
        __syncthreads();   // AT complete

        // ---- phase 2a: U = relu(AT @ W1 + b1) via HMMA ----
        {
            float acc[4][4];
            #pragma unroll
            for (int nf = 0; nf < 4; nf++)
                #pragma unroll
                for (int q = 0; q < 4; q++) acc[nf][q] = 0.f;
            #pragma unroll
            for (int ks = 0; ks < 4; ks++) {
                const int k0 = ks * 16;
                uint32_t a0 = *(const uint32_t*)(AT + (m0 + gid)     * RS + k0 + 2 * tg);
                uint32_t a1 = *(const uint32_t*)(AT + (m0 + gid + 8) * RS + k0 + 2 * tg);
                uint32_t a2 = *(const uint32_t*)(AT + (m0 + gid)     * RS + k0 + 8 + 2 * tg);
                uint32_t a3 = *(const uint32_t*)(AT + (m0 + gid + 8) * RS + k0 + 8 + 2 * tg);
                #pragma unroll
                for (int nf = 0; nf < 4; nf++) {
                    const int n = nb + nf * 8 + gid;
                    uint32_t bb0 = *(const uint32_t*)(W1h + n * RS + k0 + 2 * tg);
                    uint32_t bb1 = *(const uint32_t*)(W1h + n * RS + k0 + 8 + 2 * tg);
                    mma_16x8x16(acc[nf][0], acc[nf][1], acc[nf][2], acc[nf][3],
                                a0, a1, a2, a3, bb0, bb1);
                }
            }
            #pragma unroll
            for (int nf = 0; nf < 4; nf++) {
                const int ncol = nb + nf * 8 + 2 * tg;
                float u0 = fmaxf(acc[nf][0] + b1s[ncol], 0.f);
                float u1 = fmaxf(acc[nf][1] + b1s[ncol + 1], 0.f);
                float u2 = fmaxf(acc[nf][2] + b1s[ncol], 0.f);
                float u3 = fmaxf(acc[nf][3] + b1s[ncol + 1], 0.f);
                *(__half2*)(UT + (m0 + gid)     * RS + ncol) = __floats2half2_rn(u0, u1);
                *(__half2*)(UT + (m0 + gid + 8) * RS + ncol) = __floats2half2_rn(u2, u3);
            }
        }
        __syncthreads();   // UT complete; all AT reads done

        // ---- phase 2b: V = relu(gamma*(UT @ W2 + b2) + beta) -> hout ----
        {
            float acc[4][4];
            #pragma unroll
            for (int nf = 0; nf < 4; nf++)
                #pragma unroll
                for (int q = 0; q < 4; q++) acc[nf][q] = 0.f;
            #pragma unroll
            for (int ks = 0; ks < 4; ks++) {
                const int k0 = ks * 16;
                uint32_t a0 = *(const uint32_t*)(UT + (m0 + gid)     * RS + k0 + 2 * tg);
                uint32_t a1 = *(const uint32_t*)(UT + (m0 + gid + 8) * RS + k0 + 2 * tg);
                uint32_t a2 = *(const uint32_t*)(UT + (m0 + gid)     * RS + k0 + 8 + 2 * tg);
                uint32_t a3 = *(const uint32_t*)(UT + (m0 + gid + 8) * RS + k0 + 8 + 2 * tg);
                #pragma unroll
                for (int nf = 0; nf < 4; nf++) {
                    const int n = nb + nf * 8 + gid;
                    uint32_t bb0 = *(const uint32_t*)(W2h + n * RS + k0 + 2 * tg);
                    uint32_t bb1 = *(const uint32_t*)(W2h + n * RS + k0 + 8 + 2 * tg);
                    mma_16x8x16(acc[nf][0], acc[nf][1], acc[nf][2], acc[nf][3],
                                a0, a1, a2, a3, bb0, bb1);
                }
            }
            const int row0 = base + m0 + gid;
            const int row1 = row0 + 8;
            #pragma unroll
            for (int nf = 0; nf < 4; nf++) {
                const int ncol = nb + nf * 8 + 2 * tg;
                float v0 = fmaxf(fmaf(acc[nf][0] + b2s[ncol],     gs[ncol],     bs[ncol]),     0.f);
                float v1 = fmaxf(fmaf(acc[nf][1] + b2s[ncol + 1], gs[ncol + 1], bs[ncol + 1]), 0.f);
                float v2 = fmaxf(fmaf(acc[nf][2] + b2s[ncol],     gs[ncol],     bs[ncol]),     0.f);
                float v3 = fmaxf(fmaf(acc[nf][3] + b2s[ncol + 1], gs[ncol + 1], bs[ncol + 1]), 0.f);
                if (row0 < n_nodes)
                    *(__half2*)(hout + (size_t)row0 * 64 + ncol) = __floats2half2_rn(v0, v1);
                if (row1 < n_nodes)
                    *(__half2*)(hout + (size_t)row1 * 64 + ncol) = __floats2half2_rn(v2, v3);
            }
        }
        // NOTE: no end-of-tile sync needed — the loop-top __syncthreads()
        // (after the s_tile fetch) orders this tile's UT reads before the
        // next tile's AT/UT writes.
    }
}

// ---------------------------------------------------------------------------
__device__ __forceinline__ int lower_bound_i(const int* a, int n, int key) {
    int lo = 0, hi = n;
    while (lo < hi) {
        int mid = (lo + hi) >> 1;
        if (a[mid] < key) lo = mid + 1; else hi = mid;
    }
    return lo;
}

// fused mean-pool + head
__global__ void poolhead_kernel(const int* __restrict__ batch, int n_nodes,
                                const float* __restrict__ fc1W, const float* __restrict__ fc1b,
                                const float* __restrict__ fc2W, const float* __restrict__ fc2b,
                                float* __restrict__ out) {
    const __half* __restrict__ h = g_hB;  // final layer output lives in g_hB
    const int g = blockIdx.x;
    const int lo = lower_bound_i(batch, n_nodes, g);
    const int hi = lower_bound_i(batch, n_nodes, g + 1);
    const int c = threadIdx.x & 63;
    const int r = threadIdx.x >> 6;
    float acc = 0.f;
    for (int i = lo + r; i < hi; i += 4) acc += __half2float(h[(size_t)i * 64 + c]);
    __shared__ float sh[256];
    __shared__ float pooled[64];
    sh[threadIdx.x] = acc;
    __syncthreads();
    if (threadIdx.x < 128) sh[threadIdx.x] += sh[threadIdx.x + 128];
    __syncthreads();
    if (threadIdx.x < 64) {
        float s = sh[threadIdx.x] + sh[threadIdx.x + 64];
        float cnt = (float)(hi - lo);
        pooled[threadIdx.x] = s / fmaxf(cnt, 1.f);
    }
    __syncthreads();
    if (threadIdx.x < 32) {
        const int j = threadIdx.x;
        float a = fc1b[j];
        #pragma unroll
        for (int k = 0; k < 64; k++) a = fmaf(pooled[k], fc1W[k * 32 + j], a);
        float t = fmaxf(a, 0.f) * fc2W[j];
        #pragma unroll
        for (int o = 16; o > 0; o >>= 1) t += __shfl_down_sync(0xffffffffu, t, o);
        if (j == 0) out[g] = t + fc2b[0];
    }
}

// ---------------------------------------------------------------------------
extern "C" void kernel_launch(void* const* d_in, const int* in_sizes, int n_in,
                              void* d_out, int out_size) {
    const float* x     = (const float*)d_in[0];
    const int*   ei    = (const int*)d_in[1];
    const int*   batch = (const int*)d_in[2];
    const float* W1    = (const float*)d_in[3];
    const float* b1    = (const float*)d_in[4];
    const float* W2    = (const float*)d_in[5];
    const float* b2    = (const float*)d_in[6];
    const float* gamma = (const float*)d_in[7];
    const float* beta  = (const float*)d_in[8];
    const float* fc1W  = (const float*)d_in[9];
    const float* fc1b  = (const float*)d_in[10];
    const float* fc2W  = (const float*)d_in[11];
    const float* fc2b  = (const float*)d_in[12];
    float*       out   = (float*)d_out;

    const int N = in_sizes[0] / 64;
    const int E = in_sizes[1] / 2;
    const int G = out_size;
    const int NB = (N + SCB - 1) / SCB;

    // --- CSR build (dst -> src) + x -> half conversion ---
    init_kernel<<<(N * 64 / 4 + 255) / 256, 256>>>(x, N, N * 64);
    hist_kernel<<<1024, 256>>>(ei, E);
    bsum_kernel<<<NB, SCB>>>(N);
    bscan_kernel<<<1, 1024>>>(NB, N);
    scatter_scan_kernel<<<NB, SCB>>>(N);
    fill_kernel<<<1024, 256>>>(ei, E);

    // --- 3 fused GIN layers, ping-pong: A -> B -> A -> B ---
    const int LBLOCKS = 740;   // 5 blocks/SM; tiles via work queue
    layer_kernel<<<LBLOCKS, 256>>>(1, 2, 0,
                                   W1 + 0 * 4096, b1 + 0 * 64, W2 + 0 * 4096, b2 + 0 * 64,
                                   gamma + 0 * 64, beta + 0 * 64, N);
    layer_kernel<<<LBLOCKS, 256>>>(2, 1, 1,
                                   W1 + 1 * 4096, b1 + 1 * 64, W2 + 1 * 4096, b2 + 1 * 64,
                                   gamma + 1 * 64, beta + 1 * 64, N);
    layer_kernel<<<LBLOCKS, 256>>>(1, 2, 2,
                                   W1 + 2 * 4096, b1 + 2 * 64, W2 + 2 * 4096, b2 + 2 * 64,
                                   gamma + 2 * 64, beta + 2 * 64, N);

    // --- fused mean pool + head ---
    poolhead_kernel<<<G, 256>>>(batch, N, fc1W, fc1b, fc2W, fc2b, out);
}